// round 1
// baseline (speedup 1.0000x reference)
#include <cuda_runtime.h>
#include <cstdint>

#define BATCH 4096
#define NF 16
#define FS 64
#define EMBD 64
#define NPAIRS 120
#define K0 15424   // 2*120*64 + 64
#define N0 1024
#define N1 512
#define N2 256
#define BN_EPS 1e-5f

// ---------------- scratch (device globals; no allocations) ----------------
__device__ float g_emb[BATCH * NF * EMBD];          // 16 MB   [b][g][e]
__device__ float g_a[BATCH * NF];                   // senet gates
__device__ float g_dnn[(size_t)BATCH * K0];         // 252 MB  dnn_in
__device__ float g_h0[BATCH * N0];
__device__ float g_h1[BATCH * N1];
__device__ float g_h2[BATCH * N2];
__device__ float g_v[BATCH];
__device__ float g_lin[BATCH];
__device__ float g_mean[N0];
__device__ float g_var[N0];
__device__ float g_s2[2];

__device__ __forceinline__ float sigmoidf(float x) {
    return 1.0f / (1.0f + __expf(-x));
}

// ---------------- embedding: emb[b,g,e] = sum_f grp[b,g,f]*emb_W[g,e,f] ----
__global__ void embed_kernel(const float* __restrict__ sparse,
                             const float* __restrict__ embW) {
    __shared__ float Ws[64][65];   // [e][f]
    __shared__ float Xs[64][65];   // [row][f]
    int g = blockIdx.y;
    int b0 = blockIdx.x * 64;
    int t = threadIdx.x;

    for (int idx = t; idx < 4096; idx += 256) {
        Ws[idx >> 6][idx & 63] = embW[g * 4096 + idx];
    }
    for (int idx = t; idx < 4096; idx += 256) {
        int r = idx >> 6, f = idx & 63;
        Xs[r][f] = sparse[(size_t)(b0 + r) * 1024 + g * 64 + f];
    }
    __syncthreads();

    int rq = t >> 4, eq = t & 15;
    float acc[4][4] = {};
#pragma unroll 8
    for (int f = 0; f < 64; f++) {
        float xa[4], wb[4];
#pragma unroll
        for (int i = 0; i < 4; i++) xa[i] = Xs[rq * 4 + i][f];
#pragma unroll
        for (int j = 0; j < 4; j++) wb[j] = Ws[eq * 4 + j][f];
#pragma unroll
        for (int i = 0; i < 4; i++)
#pragma unroll
            for (int j = 0; j < 4; j++) acc[i][j] += xa[i] * wb[j];
    }
#pragma unroll
    for (int i = 0; i < 4; i++)
#pragma unroll
        for (int j = 0; j < 4; j++)
            g_emb[(size_t)(b0 + rq * 4 + i) * 1024 + g * 64 + eq * 4 + j] = acc[i][j];
}

// ---------------- SENet gates: a[b,g] ----------------
__global__ void senet_kernel(const float* __restrict__ seW1,
                             const float* __restrict__ seW2) {
    int warp = (blockIdx.x * blockDim.x + threadIdx.x) >> 5;
    int lane = threadIdx.x & 31;
    if (warp >= BATCH) return;
    const float* row = g_emb + (size_t)warp * 1024;

    float zs[16];
#pragma unroll
    for (int g = 0; g < 16; g++) {
        float s = row[g * 64 + lane] + row[g * 64 + 32 + lane];
#pragma unroll
        for (int o = 16; o; o >>= 1) s += __shfl_xor_sync(0xFFFFFFFFu, s, o);
        zs[g] = s * (1.0f / 64.0f);
    }
    // tiny MLP 16 -> 4 -> 16 (redundant per-lane, then lanes 0..15 write)
    float hv[4];
#pragma unroll
    for (int tt = 0; tt < 4; tt++) {
        float s = 0.f;
#pragma unroll
        for (int g = 0; g < 16; g++) s += zs[g] * seW1[tt * 16 + g];
        hv[tt] = fmaxf(s, 0.f);
    }
    if (lane < 16) {
        float s = 0.f;
#pragma unroll
        for (int tt = 0; tt < 4; tt++) s += hv[tt] * seW2[lane * 4 + tt];
        g_a[warp * 16 + lane] = fmaxf(s, 0.f);
    }
}

// ---------------- bilinear: writes bi_plain and bi_senet halves of dnn_in --
// bi_senet = bi_plain * a_i * a_j   (senet is a per-field scalar scale)
__global__ void bilinear_kernel(const float* __restrict__ biW) {
    __shared__ float Ws[64][65];   // [f][e]
    __shared__ float Xs[64][65];   // [row][e]  (field i)
    int p = blockIdx.y;
    int i = 0, rem = p, cnt = 15;
    while (rem >= cnt) { rem -= cnt; i++; cnt--; }
    int j = i + 1 + rem;

    int b0 = blockIdx.x * 64;
    int t = threadIdx.x;

    for (int idx = t; idx < 4096; idx += 256)
        Ws[idx >> 6][idx & 63] = biW[(size_t)p * 4096 + idx];
    for (int idx = t; idx < 4096; idx += 256) {
        int r = idx >> 6, e = idx & 63;
        Xs[r][e] = g_emb[(size_t)(b0 + r) * 1024 + i * 64 + e];
    }
    __syncthreads();

    int rq = t >> 4, fq = t & 15;
    float acc[4][4] = {};
#pragma unroll 8
    for (int e = 0; e < 64; e++) {
        float xa[4], wb[4];
#pragma unroll
        for (int i2 = 0; i2 < 4; i2++) xa[i2] = Xs[rq * 4 + i2][e];
#pragma unroll
        for (int jj = 0; jj < 4; jj++) wb[jj] = Ws[fq * 4 + jj][e];
#pragma unroll
        for (int i2 = 0; i2 < 4; i2++)
#pragma unroll
            for (int jj = 0; jj < 4; jj++) acc[i2][jj] += xa[i2] * wb[jj];
    }
#pragma unroll
    for (int i2 = 0; i2 < 4; i2++) {
        int b = b0 + rq * 4 + i2;
        float s = g_a[b * 16 + i] * g_a[b * 16 + j];
        size_t base = (size_t)b * K0 + p * 64 + fq * 4;
#pragma unroll
        for (int jj = 0; jj < 4; jj++) {
            float vj = g_emb[(size_t)b * 1024 + j * 64 + fq * 4 + jj];
            float bp = acc[i2][jj] * vj;
            g_dnn[base + jj] = bp;
            g_dnn[base + 7680 + jj] = bp * s;
        }
    }
}

// ---------------- dense copy into last 64 cols of dnn_in -------------------
__global__ void dense_copy_kernel(const float* __restrict__ dense) {
    int idx = blockIdx.x * blockDim.x + threadIdx.x;
    if (idx >= BATCH * 64) return;
    int b = idx >> 6, d = idx & 63;
    g_dnn[(size_t)b * K0 + 15360 + d] = dense[idx];
}

// ---------------- linear logit ----------------
__global__ void linear_kernel(const float* __restrict__ sparse,
                              const float* __restrict__ dense,
                              const float* __restrict__ linW,
                              const float* __restrict__ linb) {
    int warp = (blockIdx.x * blockDim.x + threadIdx.x) >> 5;
    int lane = threadIdx.x & 31;
    if (warp >= BATCH) return;
    const float* s = sparse + (size_t)warp * 1024;
    float acc = 0.f;
    for (int k = lane; k < 1024; k += 32) acc += s[k] * linW[k];
    for (int k = lane; k < 64; k += 32) acc += dense[warp * 64 + k] * linW[1024 + k];
#pragma unroll
    for (int o = 16; o; o >>= 1) acc += __shfl_xor_sync(0xFFFFFFFFu, acc, o);
    if (lane == 0) g_lin[warp] = acc + linb[0];
}

// ---------------- SGEMM: C[m,n] = sum_k A[m,k] * Bw[n,k] -------------------
// 128x128 block, 8x8/thread, BK=8, double-buffered smem
__global__ void __launch_bounds__(256, 2)
sgemm_kernel(const float* __restrict__ A, const float* __restrict__ Bw,
             float* __restrict__ C, int M, int N, int K) {
    __shared__ float As[2][8][128];
    __shared__ float Bs[2][8][128];
    int bx = blockIdx.x;  // N tile
    int by = blockIdx.y;  // M tile
    int t = threadIdx.x;

    int arow = t >> 1;
    int acol4 = (t & 1) * 4;
    const float* Ap = A + (size_t)(by * 128 + arow) * K + acol4;
    const float* Bp = Bw + (size_t)(bx * 128 + arow) * K + acol4;

    float4 av = *(const float4*)Ap;
    float4 bv = *(const float4*)Bp;
    As[0][acol4 + 0][arow] = av.x; As[0][acol4 + 1][arow] = av.y;
    As[0][acol4 + 2][arow] = av.z; As[0][acol4 + 3][arow] = av.w;
    Bs[0][acol4 + 0][arow] = bv.x; Bs[0][acol4 + 1][arow] = bv.y;
    Bs[0][acol4 + 2][arow] = bv.z; Bs[0][acol4 + 3][arow] = bv.w;
    __syncthreads();

    int tx = t & 15, ty = t >> 4;
    float acc[8][8] = {};
    int nk = K >> 3;

    for (int kt = 0; kt < nk; kt++) {
        int cur = kt & 1, nxt = cur ^ 1;
        if (kt + 1 < nk) {
            av = *(const float4*)(Ap + (size_t)(kt + 1) * 8);
            bv = *(const float4*)(Bp + (size_t)(kt + 1) * 8);
        }
#pragma unroll
        for (int k = 0; k < 8; k++) {
            float4 a0 = *(const float4*)&As[cur][k][ty * 8];
            float4 a1 = *(const float4*)&As[cur][k][ty * 8 + 4];
            float4 b0 = *(const float4*)&Bs[cur][k][tx * 8];
            float4 b1 = *(const float4*)&Bs[cur][k][tx * 8 + 4];
            float ar[8] = {a0.x, a0.y, a0.z, a0.w, a1.x, a1.y, a1.z, a1.w};
            float br[8] = {b0.x, b0.y, b0.z, b0.w, b1.x, b1.y, b1.z, b1.w};
#pragma unroll
            for (int i = 0; i < 8; i++)
#pragma unroll
                for (int j = 0; j < 8; j++) acc[i][j] += ar[i] * br[j];
        }
        if (kt + 1 < nk) {
            As[nxt][acol4 + 0][arow] = av.x; As[nxt][acol4 + 1][arow] = av.y;
            As[nxt][acol4 + 2][arow] = av.z; As[nxt][acol4 + 3][arow] = av.w;
            Bs[nxt][acol4 + 0][arow] = bv.x; Bs[nxt][acol4 + 1][arow] = bv.y;
            Bs[nxt][acol4 + 2][arow] = bv.z; Bs[nxt][acol4 + 3][arow] = bv.w;
        }
        __syncthreads();
    }

#pragma unroll
    for (int i = 0; i < 8; i++) {
        int row = by * 128 + ty * 8 + i;
        float4 c0 = {acc[i][0], acc[i][1], acc[i][2], acc[i][3]};
        float4 c1 = {acc[i][4], acc[i][5], acc[i][6], acc[i][7]};
        *(float4*)&C[(size_t)row * N + bx * 128 + tx * 8] = c0;
        *(float4*)&C[(size_t)row * N + bx * 128 + tx * 8 + 4] = c1;
    }
}

// ---------------- batchnorm stats: per-column mean/var over 4096 rows ------
__global__ void bn_stats_kernel(const float* __restrict__ X, int M, int N) {
    int c = blockIdx.x * 32 + threadIdx.x;
    float s = 0.f, q = 0.f;
    for (int r = threadIdx.y; r < M; r += blockDim.y) {
        float v = X[(size_t)r * N + c];
        s += v; q += v * v;
    }
    __shared__ float ss[8][32], qq[8][32];
    ss[threadIdx.y][threadIdx.x] = s;
    qq[threadIdx.y][threadIdx.x] = q;
    __syncthreads();
    if (threadIdx.y == 0) {
#pragma unroll
        for (int r = 1; r < 8; r++) { s += ss[r][threadIdx.x]; q += qq[r][threadIdx.x]; }
        float m = s / (float)M;
        g_mean[c] = m;
        g_var[c] = q / (float)M - m * m;
    }
}

// ---------------- apply BN + sigmoid, in place ----------------
__global__ void bn_apply_kernel(float* __restrict__ X, int M, int N) {
    int idx = blockIdx.x * blockDim.x + threadIdx.x;
    if (idx >= M * N) return;
    int c = idx % N;
    float v = (X[idx] - g_mean[c]) * rsqrtf(g_var[c] + BN_EPS);
    X[idx] = sigmoidf(v);
}

// ---------------- final W3 dot (256) per row ----------------
__global__ void w3_kernel(const float* __restrict__ W3) {
    int warp = (blockIdx.x * blockDim.x + threadIdx.x) >> 5;
    int lane = threadIdx.x & 31;
    if (warp >= BATCH) return;
    const float* h = g_h2 + (size_t)warp * 256;
    float acc = 0.f;
#pragma unroll
    for (int k = lane; k < 256; k += 32) acc += h[k] * W3[k];
#pragma unroll
    for (int o = 16; o; o >>= 1) acc += __shfl_xor_sync(0xFFFFFFFFu, acc, o);
    if (lane == 0) g_v[warp] = acc;
}

// ---------------- scalar batchnorm stats over g_v ----------------
__global__ void vstats_kernel() {
    __shared__ float ss[1024], qq[1024];
    int t = threadIdx.x;
    float s = 0.f, q = 0.f;
    for (int i = t; i < BATCH; i += 1024) { float v = g_v[i]; s += v; q += v * v; }
    ss[t] = s; qq[t] = q;
    __syncthreads();
    for (int o = 512; o; o >>= 1) {
        if (t < o) { ss[t] += ss[t + o]; qq[t] += qq[t + o]; }
        __syncthreads();
    }
    if (t == 0) {
        float m = ss[0] / (float)BATCH;
        g_s2[0] = m;
        g_s2[1] = qq[0] / (float)BATCH - m * m;
    }
}

// ---------------- final: y = sigmoid(lin + sigmoid(bn(v))) ----------------
__global__ void final_kernel(float* __restrict__ out) {
    int b = blockIdx.x * blockDim.x + threadIdx.x;
    if (b >= BATCH) return;
    float v = (g_v[b] - g_s2[0]) * rsqrtf(g_s2[1] + BN_EPS);
    float dl = sigmoidf(v);
    out[b] = sigmoidf(g_lin[b] + dl);
}

// ---------------- launch ----------------
extern "C" void kernel_launch(void* const* d_in, const int* in_sizes, int n_in,
                              void* d_out, int out_size) {
    const float* sparse = (const float*)d_in[0];
    const float* dense  = (const float*)d_in[1];
    const float* embW   = (const float*)d_in[2];
    const float* linW   = (const float*)d_in[3];
    const float* linb   = (const float*)d_in[4];
    const float* seW1   = (const float*)d_in[5];
    const float* seW2   = (const float*)d_in[6];
    const float* biW    = (const float*)d_in[7];
    const float* W0     = (const float*)d_in[8];
    const float* W1     = (const float*)d_in[10];
    const float* W2     = (const float*)d_in[12];
    const float* W3     = (const float*)d_in[14];
    // biases b0..b3 are no-ops under batchnorm (and zero); lin_b used above.

    void *p_dnn, *p_h0, *p_h1, *p_h2;
    cudaGetSymbolAddress(&p_dnn, g_dnn);
    cudaGetSymbolAddress(&p_h0, g_h0);
    cudaGetSymbolAddress(&p_h1, g_h1);
    cudaGetSymbolAddress(&p_h2, g_h2);

    embed_kernel<<<dim3(BATCH / 64, NF), 256>>>(sparse, embW);
    senet_kernel<<<BATCH / 8, 256>>>(seW1, seW2);
    bilinear_kernel<<<dim3(BATCH / 64, NPAIRS), 256>>>(biW);
    dense_copy_kernel<<<(BATCH * 64) / 256, 256>>>(dense);
    linear_kernel<<<BATCH / 8, 256>>>(sparse, dense, linW, linb);

    // layer 0: 4096 x 1024, K=15424
    sgemm_kernel<<<dim3(N0 / 128, BATCH / 128), 256>>>((const float*)p_dnn, W0, (float*)p_h0, BATCH, N0, K0);
    bn_stats_kernel<<<N0 / 32, dim3(32, 8)>>>((const float*)p_h0, BATCH, N0);
    bn_apply_kernel<<<(BATCH * N0) / 256, 256>>>((float*)p_h0, BATCH, N0);

    // layer 1: 4096 x 512, K=1024
    sgemm_kernel<<<dim3(N1 / 128, BATCH / 128), 256>>>((const float*)p_h0, W1, (float*)p_h1, BATCH, N1, N0);
    bn_stats_kernel<<<N1 / 32, dim3(32, 8)>>>((const float*)p_h1, BATCH, N1);
    bn_apply_kernel<<<(BATCH * N1) / 256, 256>>>((float*)p_h1, BATCH, N1);

    // layer 2: 4096 x 256, K=512
    sgemm_kernel<<<dim3(N2 / 128, BATCH / 128), 256>>>((const float*)p_h1, W2, (float*)p_h2, BATCH, N2, N1);
    bn_stats_kernel<<<N2 / 32, dim3(32, 8)>>>((const float*)p_h2, BATCH, N2);
    bn_apply_kernel<<<(BATCH * N2) / 256, 256>>>((float*)p_h2, BATCH, N2);

    // layer 3 + final
    w3_kernel<<<BATCH / 8, 256>>>(W3);
    vstats_kernel<<<1, 1024>>>();
    final_kernel<<<BATCH / 256, 256>>>((float*)d_out);
}

// round 2
// speedup vs baseline: 1.8428x; 1.8428x over previous
#include <cuda_runtime.h>
#include <cstdint>

#define BATCH 4096
#define NF 16
#define FS 64
#define EMBD 64
#define NPAIRS 120
#define K0 15424   // 2*120*64 + 64
#define N0 1024
#define N1 512
#define N2 256
#define BN_EPS 1e-5f

// ---------------- scratch (device globals; no allocations) ----------------
__device__ float g_emb[BATCH * NF * EMBD];          // 16 MB   [b][g][e]
__device__ float g_a[BATCH * NF];                   // senet gates
__device__ float g_dnn[(size_t)BATCH * K0];         // 252 MB  dnn_in
__device__ float g_h0[BATCH * N0];
__device__ float g_h1[BATCH * N1];
__device__ float g_h2[BATCH * N2];
__device__ float g_v[BATCH];
__device__ float g_lin[BATCH];
__device__ float g_mean[N0];
__device__ float g_var[N0];
__device__ float g_s2[2];

__device__ __forceinline__ float sigmoidf(float x) {
    return 1.0f / (1.0f + __expf(-x));
}

__device__ __forceinline__ uint32_t f2tf32(float x) {
    uint32_t r;
    asm("cvt.rna.tf32.f32 %0, %1;" : "=r"(r) : "f"(x));
    return r;
}

__device__ __forceinline__ void mma_tf32(float c[4], const uint32_t a[4], const uint32_t b[2]) {
    asm volatile(
        "mma.sync.aligned.m16n8k8.row.col.f32.tf32.tf32.f32 "
        "{%0,%1,%2,%3}, {%4,%5,%6,%7}, {%8,%9}, {%0,%1,%2,%3};"
        : "+f"(c[0]), "+f"(c[1]), "+f"(c[2]), "+f"(c[3])
        : "r"(a[0]), "r"(a[1]), "r"(a[2]), "r"(a[3]), "r"(b[0]), "r"(b[1]));
}

// ---------------- embedding: emb[b,g,e] = sum_f grp[b,g,f]*emb_W[g,e,f] ----
__global__ void embed_kernel(const float* __restrict__ sparse,
                             const float* __restrict__ embW) {
    __shared__ float Ws[64][65];   // [e][f]
    __shared__ float Xs[64][65];   // [row][f]
    int g = blockIdx.y;
    int b0 = blockIdx.x * 64;
    int t = threadIdx.x;

    for (int idx = t; idx < 4096; idx += 256) {
        Ws[idx >> 6][idx & 63] = embW[g * 4096 + idx];
    }
    for (int idx = t; idx < 4096; idx += 256) {
        int r = idx >> 6, f = idx & 63;
        Xs[r][f] = sparse[(size_t)(b0 + r) * 1024 + g * 64 + f];
    }
    __syncthreads();

    int rq = t >> 4, eq = t & 15;
    float acc[4][4] = {};
#pragma unroll 8
    for (int f = 0; f < 64; f++) {
        float xa[4], wb[4];
#pragma unroll
        for (int i = 0; i < 4; i++) xa[i] = Xs[rq * 4 + i][f];
#pragma unroll
        for (int j = 0; j < 4; j++) wb[j] = Ws[eq * 4 + j][f];
#pragma unroll
        for (int i = 0; i < 4; i++)
#pragma unroll
            for (int j = 0; j < 4; j++) acc[i][j] += xa[i] * wb[j];
    }
#pragma unroll
    for (int i = 0; i < 4; i++)
#pragma unroll
        for (int j = 0; j < 4; j++)
            g_emb[(size_t)(b0 + rq * 4 + i) * 1024 + g * 64 + eq * 4 + j] = acc[i][j];
}

// ---------------- SENet gates: a[b,g] ----------------
__global__ void senet_kernel(const float* __restrict__ seW1,
                             const float* __restrict__ seW2) {
    int warp = (blockIdx.x * blockDim.x + threadIdx.x) >> 5;
    int lane = threadIdx.x & 31;
    if (warp >= BATCH) return;
    const float* row = g_emb + (size_t)warp * 1024;

    float zs[16];
#pragma unroll
    for (int g = 0; g < 16; g++) {
        float s = row[g * 64 + lane] + row[g * 64 + 32 + lane];
#pragma unroll
        for (int o = 16; o; o >>= 1) s += __shfl_xor_sync(0xFFFFFFFFu, s, o);
        zs[g] = s * (1.0f / 64.0f);
    }
    float hv[4];
#pragma unroll
    for (int tt = 0; tt < 4; tt++) {
        float s = 0.f;
#pragma unroll
        for (int g = 0; g < 16; g++) s += zs[g] * seW1[tt * 16 + g];
        hv[tt] = fmaxf(s, 0.f);
    }
    if (lane < 16) {
        float s = 0.f;
#pragma unroll
        for (int tt = 0; tt < 4; tt++) s += hv[tt] * seW2[lane * 4 + tt];
        g_a[warp * 16 + lane] = fmaxf(s, 0.f);
    }
}

// ---------------- bilinear: writes bi_plain and bi_senet halves of dnn_in --
// bi_senet = bi_plain * a_i * a_j   (senet is a per-field scalar scale)
__global__ void bilinear_kernel(const float* __restrict__ biW) {
    __shared__ float Ws[64][65];   // [f][e]
    __shared__ float Xs[64][65];   // [row][e]  (field i)
    int p = blockIdx.y;
    int i = 0, rem = p, cnt = 15;
    while (rem >= cnt) { rem -= cnt; i++; cnt--; }
    int j = i + 1 + rem;

    int b0 = blockIdx.x * 64;
    int t = threadIdx.x;

    for (int idx = t; idx < 4096; idx += 256)
        Ws[idx >> 6][idx & 63] = biW[(size_t)p * 4096 + idx];
    for (int idx = t; idx < 4096; idx += 256) {
        int r = idx >> 6, e = idx & 63;
        Xs[r][e] = g_emb[(size_t)(b0 + r) * 1024 + i * 64 + e];
    }
    __syncthreads();

    int rq = t >> 4, fq = t & 15;
    float acc[4][4] = {};
#pragma unroll 8
    for (int e = 0; e < 64; e++) {
        float xa[4], wb[4];
#pragma unroll
        for (int i2 = 0; i2 < 4; i2++) xa[i2] = Xs[rq * 4 + i2][e];
#pragma unroll
        for (int jj = 0; jj < 4; jj++) wb[jj] = Ws[fq * 4 + jj][e];
#pragma unroll
        for (int i2 = 0; i2 < 4; i2++)
#pragma unroll
            for (int jj = 0; jj < 4; jj++) acc[i2][jj] += xa[i2] * wb[jj];
    }
#pragma unroll
    for (int i2 = 0; i2 < 4; i2++) {
        int b = b0 + rq * 4 + i2;
        float s = g_a[b * 16 + i] * g_a[b * 16 + j];
        size_t base = (size_t)b * K0 + p * 64 + fq * 4;
#pragma unroll
        for (int jj = 0; jj < 4; jj++) {
            float vj = g_emb[(size_t)b * 1024 + j * 64 + fq * 4 + jj];
            float bp = acc[i2][jj] * vj;
            g_dnn[base + jj] = bp;
            g_dnn[base + 7680 + jj] = bp * s;
        }
    }
}

// ---------------- dense copy into last 64 cols of dnn_in -------------------
__global__ void dense_copy_kernel(const float* __restrict__ dense) {
    int idx = blockIdx.x * blockDim.x + threadIdx.x;
    if (idx >= BATCH * 64) return;
    int b = idx >> 6, d = idx & 63;
    g_dnn[(size_t)b * K0 + 15360 + d] = dense[idx];
}

// ---------------- linear logit ----------------
__global__ void linear_kernel(const float* __restrict__ sparse,
                              const float* __restrict__ dense,
                              const float* __restrict__ linW,
                              const float* __restrict__ linb) {
    int warp = (blockIdx.x * blockDim.x + threadIdx.x) >> 5;
    int lane = threadIdx.x & 31;
    if (warp >= BATCH) return;
    const float* s = sparse + (size_t)warp * 1024;
    float acc = 0.f;
    for (int k = lane; k < 1024; k += 32) acc += s[k] * linW[k];
    for (int k = lane; k < 64; k += 32) acc += dense[warp * 64 + k] * linW[1024 + k];
#pragma unroll
    for (int o = 16; o; o >>= 1) acc += __shfl_xor_sync(0xFFFFFFFFu, acc, o);
    if (lane == 0) g_lin[warp] = acc + linb[0];
}

// ---------------- TF32 tensor-core GEMM: C[m,n] = sum_k A[m,k]*Bw[n,k] ----
// 128x128 block, BK=16 double-buffered, 8 warps of 64x32 warp tiles,
// mma.sync.m16n8k8 tf32. smem stride 136 words -> conflict-free frag loads.
#define TGS 136  // smem row stride (words)
__global__ void __launch_bounds__(256)
tf32_gemm_kernel(const float* __restrict__ A, const float* __restrict__ Bw,
                 float* __restrict__ C, int M, int N, int K) {
    __shared__ uint32_t As[2][16][TGS];
    __shared__ uint32_t Bs[2][16][TGS];

    int bx = blockIdx.x;  // N tile
    int by = blockIdx.y;  // M tile
    int t = threadIdx.x;
    int lane = t & 31;
    int warp = t >> 5;
    int gid = lane >> 2;   // 0..7
    int tig = lane & 3;    // 0..3
    int warp_m = warp & 1;     // 2 tiles of 64 rows
    int warp_n = warp >> 1;    // 4 tiles of 32 cols

    // gmem load mapping: thread loads 8 floats (2x float4) of one row
    int lrow = t >> 1;
    int lcb = (t & 1) * 8;
    const float* Ap = A + (size_t)(by * 128 + lrow) * K + lcb;
    const float* Bp = Bw + (size_t)(bx * 128 + lrow) * K + lcb;

    float4 av0 = *(const float4*)Ap;
    float4 av1 = *(const float4*)(Ap + 4);
    float4 bv0 = *(const float4*)Bp;
    float4 bv1 = *(const float4*)(Bp + 4);
    {
        float a8[8] = {av0.x, av0.y, av0.z, av0.w, av1.x, av1.y, av1.z, av1.w};
        float b8[8] = {bv0.x, bv0.y, bv0.z, bv0.w, bv1.x, bv1.y, bv1.z, bv1.w};
#pragma unroll
        for (int i = 0; i < 8; i++) {
            As[0][lcb + i][lrow] = f2tf32(a8[i]);
            Bs[0][lcb + i][lrow] = f2tf32(b8[i]);
        }
    }
    __syncthreads();

    float acc[4][4][4] = {};
    int nk = K >> 4;

    for (int kt = 0; kt < nk; kt++) {
        int cur = kt & 1, nxt = cur ^ 1;
        if (kt + 1 < nk) {
            const float* Ap2 = Ap + (size_t)(kt + 1) * 16;
            const float* Bp2 = Bp + (size_t)(kt + 1) * 16;
            av0 = *(const float4*)Ap2;
            av1 = *(const float4*)(Ap2 + 4);
            bv0 = *(const float4*)Bp2;
            bv1 = *(const float4*)(Bp2 + 4);
        }

#pragma unroll
        for (int ks = 0; ks < 16; ks += 8) {
            uint32_t af[4][4];
            uint32_t bf[4][2];
#pragma unroll
            for (int mt = 0; mt < 4; mt++) {
                int m = warp_m * 64 + mt * 16 + gid;
                af[mt][0] = As[cur][ks + tig][m];
                af[mt][1] = As[cur][ks + tig][m + 8];
                af[mt][2] = As[cur][ks + tig + 4][m];
                af[mt][3] = As[cur][ks + tig + 4][m + 8];
            }
#pragma unroll
            for (int nt = 0; nt < 4; nt++) {
                int n = warp_n * 32 + nt * 8 + gid;
                bf[nt][0] = Bs[cur][ks + tig][n];
                bf[nt][1] = Bs[cur][ks + tig + 4][n];
            }
#pragma unroll
            for (int mt = 0; mt < 4; mt++)
#pragma unroll
                for (int nt = 0; nt < 4; nt++)
                    mma_tf32(acc[mt][nt], af[mt], bf[nt]);
        }

        if (kt + 1 < nk) {
            float a8[8] = {av0.x, av0.y, av0.z, av0.w, av1.x, av1.y, av1.z, av1.w};
            float b8[8] = {bv0.x, bv0.y, bv0.z, bv0.w, bv1.x, bv1.y, bv1.z, bv1.w};
#pragma unroll
            for (int i = 0; i < 8; i++) {
                As[nxt][lcb + i][lrow] = f2tf32(a8[i]);
                Bs[nxt][lcb + i][lrow] = f2tf32(b8[i]);
            }
        }
        __syncthreads();
    }

    // epilogue: c0,c1 -> (row, 2*tig), c2,c3 -> (row+8, 2*tig)
#pragma unroll
    for (int mt = 0; mt < 4; mt++) {
#pragma unroll
        for (int nt = 0; nt < 4; nt++) {
            int row = by * 128 + warp_m * 64 + mt * 16 + gid;
            int col = bx * 128 + warp_n * 32 + nt * 8 + 2 * tig;
            float2 lo = {acc[mt][nt][0], acc[mt][nt][1]};
            float2 hi = {acc[mt][nt][2], acc[mt][nt][3]};
            *(float2*)&C[(size_t)row * N + col] = lo;
            *(float2*)&C[(size_t)(row + 8) * N + col] = hi;
        }
    }
}

// ---------------- batchnorm stats: per-column mean/var over 4096 rows ------
__global__ void bn_stats_kernel(const float* __restrict__ X, int M, int N) {
    int c = blockIdx.x * 32 + threadIdx.x;
    float s = 0.f, q = 0.f;
    for (int r = threadIdx.y; r < M; r += blockDim.y) {
        float v = X[(size_t)r * N + c];
        s += v; q += v * v;
    }
    __shared__ float ss[8][32], qq[8][32];
    ss[threadIdx.y][threadIdx.x] = s;
    qq[threadIdx.y][threadIdx.x] = q;
    __syncthreads();
    if (threadIdx.y == 0) {
#pragma unroll
        for (int r = 1; r < 8; r++) { s += ss[r][threadIdx.x]; q += qq[r][threadIdx.x]; }
        float m = s / (float)M;
        g_mean[c] = m;
        g_var[c] = q / (float)M - m * m;
    }
}

// ---------------- apply BN + sigmoid, in place ----------------
__global__ void bn_apply_kernel(float* __restrict__ X, int M, int N) {
    int idx = blockIdx.x * blockDim.x + threadIdx.x;
    if (idx >= M * N) return;
    int c = idx % N;
    float v = (X[idx] - g_mean[c]) * rsqrtf(g_var[c] + BN_EPS);
    X[idx] = sigmoidf(v);
}

// ---------------- final W3 dot (256) per row ----------------
__global__ void w3_kernel(const float* __restrict__ W3) {
    int warp = (blockIdx.x * blockDim.x + threadIdx.x) >> 5;
    int lane = threadIdx.x & 31;
    if (warp >= BATCH) return;
    const float* h = g_h2 + (size_t)warp * 256;
    float acc = 0.f;
#pragma unroll
    for (int k = lane; k < 256; k += 32) acc += h[k] * W3[k];
#pragma unroll
    for (int o = 16; o; o >>= 1) acc += __shfl_xor_sync(0xFFFFFFFFu, acc, o);
    if (lane == 0) g_v[warp] = acc;
}

// ---------------- scalar batchnorm stats over g_v ----------------
__global__ void vstats_kernel() {
    __shared__ float ss[1024], qq[1024];
    int t = threadIdx.x;
    float s = 0.f, q = 0.f;
    for (int i = t; i < BATCH; i += 1024) { float v = g_v[i]; s += v; q += v * v; }
    ss[t] = s; qq[t] = q;
    __syncthreads();
    for (int o = 512; o; o >>= 1) {
        if (t < o) { ss[t] += ss[t + o]; qq[t] += qq[t + o]; }
        __syncthreads();
    }
    if (t == 0) {
        float m = ss[0] / (float)BATCH;
        g_s2[0] = m;
        g_s2[1] = qq[0] / (float)BATCH - m * m;
    }
}

// ---------------- final: y = sigmoid(lin + sigmoid(bn(v))) ----------------
__global__ void final_kernel(float* __restrict__ out) {
    int b = blockIdx.x * blockDim.x + threadIdx.x;
    if (b >= BATCH) return;
    float v = (g_v[b] - g_s2[0]) * rsqrtf(g_s2[1] + BN_EPS);
    float dl = sigmoidf(v);
    out[b] = sigmoidf(g_lin[b] + dl);
}

// ---------------- launch ----------------
extern "C" void kernel_launch(void* const* d_in, const int* in_sizes, int n_in,
                              void* d_out, int out_size) {
    const float* sparse = (const float*)d_in[0];
    const float* dense  = (const float*)d_in[1];
    const float* embW   = (const float*)d_in[2];
    const float* linW   = (const float*)d_in[3];
    const float* linb   = (const float*)d_in[4];
    const float* seW1   = (const float*)d_in[5];
    const float* seW2   = (const float*)d_in[6];
    const float* biW    = (const float*)d_in[7];
    const float* W0     = (const float*)d_in[8];
    const float* W1     = (const float*)d_in[10];
    const float* W2     = (const float*)d_in[12];
    const float* W3     = (const float*)d_in[14];
    // biases b0..b3 are no-ops under batchnorm (and zero); lin_b used above.

    void *p_dnn, *p_h0, *p_h1, *p_h2;
    cudaGetSymbolAddress(&p_dnn, g_dnn);
    cudaGetSymbolAddress(&p_h0, g_h0);
    cudaGetSymbolAddress(&p_h1, g_h1);
    cudaGetSymbolAddress(&p_h2, g_h2);

    embed_kernel<<<dim3(BATCH / 64, NF), 256>>>(sparse, embW);
    senet_kernel<<<BATCH / 8, 256>>>(seW1, seW2);
    bilinear_kernel<<<dim3(BATCH / 64, NPAIRS), 256>>>(biW);
    dense_copy_kernel<<<(BATCH * 64) / 256, 256>>>(dense);
    linear_kernel<<<BATCH / 8, 256>>>(sparse, dense, linW, linb);

    // layer 0: 4096 x 1024, K=15424
    tf32_gemm_kernel<<<dim3(N0 / 128, BATCH / 128), 256>>>((const float*)p_dnn, W0, (float*)p_h0, BATCH, N0, K0);
    bn_stats_kernel<<<N0 / 32, dim3(32, 8)>>>((const float*)p_h0, BATCH, N0);
    bn_apply_kernel<<<(BATCH * N0) / 256, 256>>>((float*)p_h0, BATCH, N0);

    // layer 1: 4096 x 512, K=1024
    tf32_gemm_kernel<<<dim3(N1 / 128, BATCH / 128), 256>>>((const float*)p_h0, W1, (float*)p_h1, BATCH, N1, N0);
    bn_stats_kernel<<<N1 / 32, dim3(32, 8)>>>((const float*)p_h1, BATCH, N1);
    bn_apply_kernel<<<(BATCH * N1) / 256, 256>>>((float*)p_h1, BATCH, N1);

    // layer 2: 4096 x 256, K=512
    tf32_gemm_kernel<<<dim3(N2 / 128, BATCH / 128), 256>>>((const float*)p_h1, W2, (float*)p_h2, BATCH, N2, N1);
    bn_stats_kernel<<<N2 / 32, dim3(32, 8)>>>((const float*)p_h2, BATCH, N2);
    bn_apply_kernel<<<(BATCH * N2) / 256, 256>>>((float*)p_h2, BATCH, N2);

    // layer 3 + final
    w3_kernel<<<BATCH / 8, 256>>>(W3);
    vstats_kernel<<<1, 1024>>>();
    final_kernel<<<BATCH / 256, 256>>>((float*)d_out);
}

// round 4
// speedup vs baseline: 3.8228x; 2.0744x over previous
#include <cuda_runtime.h>
#include <cuda_fp16.h>
#include <cstdint>

#define BATCH 4096
#define NF 16
#define FS 64
#define EMBD 64
#define NPAIRS 120
#define K0 15424   // 2*120*64 + 64
#define N0 1024
#define N1 512
#define N2 256
#define BN_EPS 1e-5f

// ---------------- scratch (device globals; no allocations) ----------------
__device__ __align__(16) float  g_emb[BATCH * NF * EMBD];
__device__ float  g_a[BATCH * NF];
__device__ __align__(16) __half g_dnn[(size_t)BATCH * K0];     // 126 MB, fp16 dnn_in
__device__ __align__(16) __half g_W0h[(size_t)N0 * K0];        // 31.6 MB
__device__ __align__(16) __half g_W1h[N1 * N0];
__device__ __align__(16) __half g_W2h[N2 * N1];
__device__ __align__(16) float  g_h0[BATCH * N0];
__device__ __align__(16) float  g_h1[BATCH * N1];
__device__ __align__(16) float  g_h2[BATCH * N2];
__device__ __align__(16) __half g_h0h[BATCH * N0];
__device__ __align__(16) __half g_h1h[BATCH * N1];
__device__ __align__(16) __half g_h2h[BATCH * N2];
__device__ float g_v[BATCH];
__device__ float g_lin[BATCH];
__device__ float g_mean[N0];
__device__ float g_var[N0];
__device__ float g_s2[2];

__device__ __forceinline__ float sigmoidf(float x) {
    return 1.0f / (1.0f + __expf(-x));
}

__device__ __forceinline__ uint32_t smem_u32(const void* p) {
    uint32_t a;
    asm("{ .reg .u64 t; cvta.to.shared.u64 t, %1; cvt.u32.u64 %0, t; }" : "=r"(a) : "l"(p));
    return a;
}

__device__ __forceinline__ void mma_f16(float c[4], const uint32_t a[4], const uint32_t b[2]) {
    asm volatile(
        "mma.sync.aligned.m16n8k16.row.col.f32.f16.f16.f32 "
        "{%0,%1,%2,%3}, {%4,%5,%6,%7}, {%8,%9}, {%0,%1,%2,%3};"
        : "+f"(c[0]), "+f"(c[1]), "+f"(c[2]), "+f"(c[3])
        : "r"(a[0]), "r"(a[1]), "r"(a[2]), "r"(a[3]), "r"(b[0]), "r"(b[1]));
}

__device__ __forceinline__ void ldsm_x4(uint32_t r[4], uint32_t addr) {
    asm volatile("ldmatrix.sync.aligned.m8n8.x4.shared.b16 {%0,%1,%2,%3}, [%4];"
        : "=r"(r[0]), "=r"(r[1]), "=r"(r[2]), "=r"(r[3]) : "r"(addr));
}
__device__ __forceinline__ void ldsm_x2(uint32_t r[2], uint32_t addr) {
    asm volatile("ldmatrix.sync.aligned.m8n8.x2.shared.b16 {%0,%1}, [%2];"
        : "=r"(r[0]), "=r"(r[1]) : "r"(addr));
}
__device__ __forceinline__ void cp_async16(uint32_t dst, const void* src) {
    asm volatile("cp.async.cg.shared.global [%0], [%1], 16;" :: "r"(dst), "l"(src));
}
#define CP_COMMIT() asm volatile("cp.async.commit_group;" ::: "memory")
#define CP_WAIT(n)  asm volatile("cp.async.wait_group %0;" :: "n"(n) : "memory")

// ================= FP16 tensor-core GEMM =================
// C[m,n] = sum_k A[m,k] * B[n,k]; A,B fp16 row-major (K contiguous), C fp32.
// CTA tile 256x128, BK=64, 3-stage cp.async pipeline, 512 thr (4x4 warps, 64x32).
#define GTM 256
#define GTN 128
#define GBK 64
#define GNS 3
#define ROWB 144                 // smem row stride bytes (64 halves + 8 pad)
#define A_ST (GTM * ROWB)        // 36864
#define B_ST (GTN * ROWB)        // 18432
#define STB  (A_ST + B_ST)       // 55296
#define GSMEM (GNS * STB)        // 165888

__global__ void __launch_bounds__(512, 1)
hgemm_kernel(const __half* __restrict__ A, const __half* __restrict__ Bw,
             float* __restrict__ C, int N, int K) {
    extern __shared__ __align__(128) char smem[];
    uint32_t sb = smem_u32(smem);
    int t = threadIdx.x;
    int lane = t & 31, warp = t >> 5;
    int wm = warp >> 2;        // 0..3 -> 64 rows each
    int wn = warp & 3;         // 0..3 -> 32 cols each

    const __half* Ag = A + (size_t)(blockIdx.y * GTM) * K;
    const __half* Bg = Bw + (size_t)(blockIdx.x * GTN) * K;
    int nk = K / GBK;

    // ldmatrix lane base offsets (within a stage)
    int j = lane >> 3, r8 = lane & 7;
    uint32_t a_off = (uint32_t)((wm * 64 + (j & 1) * 8 + r8) * ROWB + (j >> 1) * 16);
    uint32_t b_off = (uint32_t)(A_ST + (wn * 32 + r8) * ROWB + (j & 1) * 16);

    // stage loader: 2048 A-chunks + 1024 B-chunks of 16B, 6 per thread
    auto load_stage = [&](int slot, int kt) {
        uint32_t sdst = sb + slot * STB;
        int koff = kt * GBK;
#pragma unroll
        for (int c0 = 0; c0 < 3072; c0 += 512) {
            int c = c0 + t;
            if (c < 2048) {
                int r = c >> 3, ch = c & 7;
                cp_async16(sdst + r * ROWB + ch * 16, Ag + (size_t)r * K + koff + ch * 8);
            } else {
                int c2 = c - 2048;
                int r = c2 >> 3, ch = c2 & 7;
                cp_async16(sdst + A_ST + r * ROWB + ch * 16, Bg + (size_t)r * K + koff + ch * 8);
            }
        }
    };

    for (int s = 0; s < GNS - 1; s++) { load_stage(s, s); CP_COMMIT(); }

    float acc[4][4][4] = {};

    for (int kt = 0; kt < nk; kt++) {
        CP_WAIT(GNS - 2);
        __syncthreads();
        uint32_t sbase = sb + (kt % GNS) * STB;
#pragma unroll
        for (int ks = 0; ks < 4; ks++) {            // 4 x k16 within BK=64
            uint32_t kb = ks * 32;
            uint32_t aF[4][4], bF[4][2];
#pragma unroll
            for (int mt = 0; mt < 4; mt++)
                ldsm_x4(aF[mt], sbase + a_off + mt * 16 * ROWB + kb);
#pragma unroll
            for (int nt = 0; nt < 4; nt++)
                ldsm_x2(bF[nt], sbase + b_off + nt * 8 * ROWB + kb);
#pragma unroll
            for (int mt = 0; mt < 4; mt++)
#pragma unroll
                for (int nt = 0; nt < 4; nt++)
                    mma_f16(acc[mt][nt], aF[mt], bF[nt]);
        }
        __syncthreads();
        if (kt + GNS - 1 < nk) load_stage((kt + GNS - 1) % GNS, kt + GNS - 1);
        CP_COMMIT();
    }

    // epilogue
    int g = lane >> 2, tig = lane & 3;
#pragma unroll
    for (int mt = 0; mt < 4; mt++) {
#pragma unroll
        for (int nt = 0; nt < 4; nt++) {
            int row = blockIdx.y * GTM + wm * 64 + mt * 16 + g;
            int col = blockIdx.x * GTN + wn * 32 + nt * 8 + 2 * tig;
            float2 lo = {acc[mt][nt][0], acc[mt][nt][1]};
            float2 hi = {acc[mt][nt][2], acc[mt][nt][3]};
            *(float2*)&C[(size_t)row * N + col] = lo;
            *(float2*)&C[(size_t)(row + 8) * N + col] = hi;
        }
    }
}

// ---------------- f32 -> f16 weight conversion ----------------
__global__ void f2h_kernel(const float* __restrict__ src, __half* __restrict__ dst, int n) {
    int i = (blockIdx.x * blockDim.x + threadIdx.x) * 4;
    if (i >= n) return;
    float4 v = *(const float4*)(src + i);
    __half2* d = (__half2*)(dst + i);
    d[0] = __floats2half2_rn(v.x, v.y);
    d[1] = __floats2half2_rn(v.z, v.w);
}

// ---------------- embedding ----------------
__global__ void embed_kernel(const float* __restrict__ sparse,
                             const float* __restrict__ embW) {
    __shared__ float Ws[64][65];
    __shared__ float Xs[64][65];
    int g = blockIdx.y;
    int b0 = blockIdx.x * 64;
    int t = threadIdx.x;

    for (int idx = t; idx < 4096; idx += 256)
        Ws[idx >> 6][idx & 63] = embW[g * 4096 + idx];
    for (int idx = t; idx < 4096; idx += 256) {
        int r = idx >> 6, f = idx & 63;
        Xs[r][f] = sparse[(size_t)(b0 + r) * 1024 + g * 64 + f];
    }
    __syncthreads();

    int rq = t >> 4, eq = t & 15;
    float acc[4][4] = {};
#pragma unroll 8
    for (int f = 0; f < 64; f++) {
        float xa[4], wb[4];
#pragma unroll
        for (int i = 0; i < 4; i++) xa[i] = Xs[rq * 4 + i][f];
#pragma unroll
        for (int j = 0; j < 4; j++) wb[j] = Ws[eq * 4 + j][f];
#pragma unroll
        for (int i = 0; i < 4; i++)
#pragma unroll
            for (int j = 0; j < 4; j++) acc[i][j] += xa[i] * wb[j];
    }
#pragma unroll
    for (int i = 0; i < 4; i++)
#pragma unroll
        for (int j = 0; j < 4; j++)
            g_emb[(size_t)(b0 + rq * 4 + i) * 1024 + g * 64 + eq * 4 + j] = acc[i][j];
}

// ---------------- SENet gates ----------------
__global__ void senet_kernel(const float* __restrict__ seW1,
                             const float* __restrict__ seW2) {
    int warp = (blockIdx.x * blockDim.x + threadIdx.x) >> 5;
    int lane = threadIdx.x & 31;
    if (warp >= BATCH) return;
    const float* row = g_emb + (size_t)warp * 1024;

    float zs[16];
#pragma unroll
    for (int g = 0; g < 16; g++) {
        float s = row[g * 64 + lane] + row[g * 64 + 32 + lane];
#pragma unroll
        for (int o = 16; o; o >>= 1) s += __shfl_xor_sync(0xFFFFFFFFu, s, o);
        zs[g] = s * (1.0f / 64.0f);
    }
    float hv[4];
#pragma unroll
    for (int tt = 0; tt < 4; tt++) {
        float s = 0.f;
#pragma unroll
        for (int g = 0; g < 16; g++) s += zs[g] * seW1[tt * 16 + g];
        hv[tt] = fmaxf(s, 0.f);
    }
    if (lane < 16) {
        float s = 0.f;
#pragma unroll
        for (int tt = 0; tt < 4; tt++) s += hv[tt] * seW2[lane * 4 + tt];
        g_a[warp * 16 + lane] = fmaxf(s, 0.f);
    }
}

// ---------------- bilinear (writes fp16 dnn_in halves) ----------------
__global__ void bilinear_kernel(const float* __restrict__ biW) {
    __shared__ float Ws[64][65];
    __shared__ float Xs[64][65];
    int p = blockIdx.y;
    int i = 0, rem = p, cnt = 15;
    while (rem >= cnt) { rem -= cnt; i++; cnt--; }
    int j = i + 1 + rem;

    int b0 = blockIdx.x * 64;
    int t = threadIdx.x;

    for (int idx = t; idx < 4096; idx += 256)
        Ws[idx >> 6][idx & 63] = biW[(size_t)p * 4096 + idx];
    for (int idx = t; idx < 4096; idx += 256) {
        int r = idx >> 6, e = idx & 63;
        Xs[r][e] = g_emb[(size_t)(b0 + r) * 1024 + i * 64 + e];
    }
    __syncthreads();

    int rq = t >> 4, fq = t & 15;
    float acc[4][4] = {};
#pragma unroll 8
    for (int e = 0; e < 64; e++) {
        float xa[4], wb[4];
#pragma unroll
        for (int i2 = 0; i2 < 4; i2++) xa[i2] = Xs[rq * 4 + i2][e];
#pragma unroll
        for (int jj = 0; jj < 4; jj++) wb[jj] = Ws[fq * 4 + jj][e];
#pragma unroll
        for (int i2 = 0; i2 < 4; i2++)
#pragma unroll
            for (int jj = 0; jj < 4; jj++) acc[i2][jj] += xa[i2] * wb[jj];
    }
#pragma unroll
    for (int i2 = 0; i2 < 4; i2++) {
        int b = b0 + rq * 4 + i2;
        float s = g_a[b * 16 + i] * g_a[b * 16 + j];
        size_t base = (size_t)b * K0 + p * 64 + fq * 4;
#pragma unroll
        for (int jj = 0; jj < 4; jj++) {
            float vj = g_emb[(size_t)b * 1024 + j * 64 + fq * 4 + jj];
            float bp = acc[i2][jj] * vj;
            g_dnn[base + jj] = __float2half_rn(bp);
            g_dnn[base + 7680 + jj] = __float2half_rn(bp * s);
        }
    }
}

// ---------------- dense copy (fp16) ----------------
__global__ void dense_copy_kernel(const float* __restrict__ dense) {
    int idx = blockIdx.x * blockDim.x + threadIdx.x;
    if (idx >= BATCH * 64) return;
    int b = idx >> 6, d = idx & 63;
    g_dnn[(size_t)b * K0 + 15360 + d] = __float2half_rn(dense[idx]);
}

// ---------------- linear logit ----------------
__global__ void linear_kernel(const float* __restrict__ sparse,
                              const float* __restrict__ dense,
                              const float* __restrict__ linW,
                              const float* __restrict__ linb) {
    int warp = (blockIdx.x * blockDim.x + threadIdx.x) >> 5;
    int lane = threadIdx.x & 31;
    if (warp >= BATCH) return;
    const float* s = sparse + (size_t)warp * 1024;
    float acc = 0.f;
    for (int k = lane; k < 1024; k += 32) acc += s[k] * linW[k];
    for (int k = lane; k < 64; k += 32) acc += dense[warp * 64 + k] * linW[1024 + k];
#pragma unroll
    for (int o = 16; o; o >>= 1) acc += __shfl_xor_sync(0xFFFFFFFFu, acc, o);
    if (lane == 0) g_lin[warp] = acc + linb[0];
}

// ---------------- batchnorm stats ----------------
__global__ void bn_stats_kernel(const float* __restrict__ X, int M, int N) {
    int c = blockIdx.x * 32 + threadIdx.x;
    float s = 0.f, q = 0.f;
    for (int r = threadIdx.y; r < M; r += blockDim.y) {
        float v = X[(size_t)r * N + c];
        s += v; q += v * v;
    }
    __shared__ float ss[8][32], qq[8][32];
    ss[threadIdx.y][threadIdx.x] = s;
    qq[threadIdx.y][threadIdx.x] = q;
    __syncthreads();
    if (threadIdx.y == 0) {
#pragma unroll
        for (int r = 1; r < 8; r++) { s += ss[r][threadIdx.x]; q += qq[r][threadIdx.x]; }
        float m = s / (float)M;
        g_mean[c] = m;
        g_var[c] = q / (float)M - m * m;
    }
}

// ---------------- apply BN + sigmoid -> fp16 out ----------------
__global__ void bn_apply_kernel(const float* __restrict__ X, __half* __restrict__ Xh,
                                int M, int N) {
    int idx = blockIdx.x * blockDim.x + threadIdx.x;
    if (idx >= M * N) return;
    int c = idx % N;
    float v = (X[idx] - g_mean[c]) * rsqrtf(g_var[c] + BN_EPS);
    Xh[idx] = __float2half_rn(sigmoidf(v));
}

// ---------------- W3 dot (reads fp16 h2) ----------------
__global__ void w3_kernel(const float* __restrict__ W3) {
    int warp = (blockIdx.x * blockDim.x + threadIdx.x) >> 5;
    int lane = threadIdx.x & 31;
    if (warp >= BATCH) return;
    const __half* h = g_h2h + (size_t)warp * 256;
    float acc = 0.f;
#pragma unroll
    for (int k = lane; k < 256; k += 32) acc += __half2float(h[k]) * W3[k];
#pragma unroll
    for (int o = 16; o; o >>= 1) acc += __shfl_xor_sync(0xFFFFFFFFu, acc, o);
    if (lane == 0) g_v[warp] = acc;
}

// ---------------- scalar BN stats ----------------
__global__ void vstats_kernel() {
    __shared__ float ss[1024], qq[1024];
    int t = threadIdx.x;
    float s = 0.f, q = 0.f;
    for (int i = t; i < BATCH; i += 1024) { float v = g_v[i]; s += v; q += v * v; }
    ss[t] = s; qq[t] = q;
    __syncthreads();
    for (int o = 512; o; o >>= 1) {
        if (t < o) { ss[t] += ss[t + o]; qq[t] += qq[t + o]; }
        __syncthreads();
    }
    if (t == 0) {
        float m = ss[0] / (float)BATCH;
        g_s2[0] = m;
        g_s2[1] = qq[0] / (float)BATCH - m * m;
    }
}

// ---------------- final ----------------
__global__ void final_kernel(float* __restrict__ out) {
    int b = blockIdx.x * blockDim.x + threadIdx.x;
    if (b >= BATCH) return;
    float v = (g_v[b] - g_s2[0]) * rsqrtf(g_s2[1] + BN_EPS);
    float dl = sigmoidf(v);
    out[b] = sigmoidf(g_lin[b] + dl);
}

// ---------------- launch ----------------
extern "C" void kernel_launch(void* const* d_in, const int* in_sizes, int n_in,
                              void* d_out, int out_size) {
    const float* sparse = (const float*)d_in[0];
    const float* dense  = (const float*)d_in[1];
    const float* embW   = (const float*)d_in[2];
    const float* linW   = (const float*)d_in[3];
    const float* linb   = (const float*)d_in[4];
    const float* seW1   = (const float*)d_in[5];
    const float* seW2   = (const float*)d_in[6];
    const float* biW    = (const float*)d_in[7];
    const float* W0     = (const float*)d_in[8];
    const float* W1     = (const float*)d_in[10];
    const float* W2     = (const float*)d_in[12];
    const float* W3     = (const float*)d_in[14];

    void *p_dnn, *p_W0h, *p_W1h, *p_W2h, *p_h0, *p_h1, *p_h2, *p_h0h, *p_h1h, *p_h2h;
    cudaGetSymbolAddress(&p_dnn, g_dnn);
    cudaGetSymbolAddress(&p_W0h, g_W0h);
    cudaGetSymbolAddress(&p_W1h, g_W1h);
    cudaGetSymbolAddress(&p_W2h, g_W2h);
    cudaGetSymbolAddress(&p_h0, g_h0);
    cudaGetSymbolAddress(&p_h1, g_h1);
    cudaGetSymbolAddress(&p_h2, g_h2);
    cudaGetSymbolAddress(&p_h0h, g_h0h);
    cudaGetSymbolAddress(&p_h1h, g_h1h);
    cudaGetSymbolAddress(&p_h2h, g_h2h);

    cudaFuncSetAttribute(hgemm_kernel, cudaFuncAttributeMaxDynamicSharedMemorySize, GSMEM);

    // weight conversions (f32 -> f16)
    f2h_kernel<<<(N0 * K0 / 4 + 255) / 256, 256>>>(W0, (__half*)p_W0h, N0 * K0);
    f2h_kernel<<<(N1 * N0 / 4 + 255) / 256, 256>>>(W1, (__half*)p_W1h, N1 * N0);
    f2h_kernel<<<(N2 * N1 / 4 + 255) / 256, 256>>>(W2, (__half*)p_W2h, N2 * N1);

    embed_kernel<<<dim3(BATCH / 64, NF), 256>>>(sparse, embW);
    senet_kernel<<<BATCH / 8, 256>>>(seW1, seW2);
    bilinear_kernel<<<dim3(BATCH / 64, NPAIRS), 256>>>(biW);
    dense_copy_kernel<<<(BATCH * 64) / 256, 256>>>(dense);
    linear_kernel<<<BATCH / 8, 256>>>(sparse, dense, linW, linb);

    // layer 0: 4096 x 1024, K=15424
    hgemm_kernel<<<dim3(N0 / GTN, BATCH / GTM), 512, GSMEM>>>(
        (const __half*)p_dnn, (const __half*)p_W0h, (float*)p_h0, N0, K0);
    bn_stats_kernel<<<N0 / 32, dim3(32, 8)>>>((const float*)p_h0, BATCH, N0);
    bn_apply_kernel<<<(BATCH * N0) / 256, 256>>>((const float*)p_h0, (__half*)p_h0h, BATCH, N0);

    // layer 1: 4096 x 512, K=1024
    hgemm_kernel<<<dim3(N1 / GTN, BATCH / GTM), 512, GSMEM>>>(
        (const __half*)p_h0h, (const __half*)p_W1h, (float*)p_h1, N1, N0);
    bn_stats_kernel<<<N1 / 32, dim3(32, 8)>>>((const float*)p_h1, BATCH, N1);
    bn_apply_kernel<<<(BATCH * N1) / 256, 256>>>((const float*)p_h1, (__half*)p_h1h, BATCH, N1);

    // layer 2: 4096 x 256, K=512
    hgemm_kernel<<<dim3(N2 / GTN, BATCH / GTM), 512, GSMEM>>>(
        (const __half*)p_h1h, (const __half*)p_W2h, (float*)p_h2, N2, N1);
    bn_stats_kernel<<<N2 / 32, dim3(32, 8)>>>((const float*)p_h2, BATCH, N2);
    bn_apply_kernel<<<(BATCH * N2) / 256, 256>>>((const float*)p_h2, (__half*)p_h2h, BATCH, N2);

    // layer 3 + final
    w3_kernel<<<BATCH / 8, 256>>>(W3);
    vstats_kernel<<<1, 1024>>>();
    final_kernel<<<BATCH / 256, 256>>>((float*)d_out);
}

// round 5
// speedup vs baseline: 4.3398x; 1.1352x over previous
#include <cuda_runtime.h>
#include <cuda_fp16.h>
#include <cstdint>

#define BATCH 4096
#define NF 16
#define FS 64
#define EMBD 64
#define NPAIRS 120
#define K0 15424   // 2*120*64 + 64
#define N0 1024
#define N1 512
#define N2 256
#define BN_EPS 1e-5f

// ---------------- scratch (device globals; no allocations) ----------------
__device__ __align__(16) __half g_embh[BATCH * NF * EMBD];     // 8 MB fp16 emb
__device__ float  g_a[BATCH * NF];
__device__ __align__(16) __half g_dnn[(size_t)BATCH * K0];     // 126 MB fp16 dnn_in
__device__ __align__(16) __half g_W0h[(size_t)N0 * K0];
__device__ __align__(16) __half g_W1h[N1 * N0];
__device__ __align__(16) __half g_W2h[N2 * N1];
__device__ __align__(16) __half g_biWh[NPAIRS * EMBD * EMBD];  // 1 MB
__device__ __align__(16) float  g_h0[BATCH * N0];
__device__ __align__(16) float  g_h1[BATCH * N1];
__device__ __align__(16) float  g_h2[BATCH * N2];
__device__ __align__(16) __half g_h0h[BATCH * N0];
__device__ __align__(16) __half g_h1h[BATCH * N1];
__device__ __align__(16) __half g_h2h[BATCH * N2];
__device__ float g_v[BATCH];
__device__ float g_lin[BATCH];
__device__ float g_mean[N0];
__device__ float g_var[N0];
__device__ float g_s2[2];

__device__ __forceinline__ float sigmoidf(float x) {
    return 1.0f / (1.0f + __expf(-x));
}

__device__ __forceinline__ uint32_t smem_u32(const void* p) {
    uint32_t a;
    asm("{ .reg .u64 t; cvta.to.shared.u64 t, %1; cvt.u32.u64 %0, t; }" : "=r"(a) : "l"(p));
    return a;
}

__device__ __forceinline__ void mma_f16(float c[4], const uint32_t a[4], const uint32_t b[2]) {
    asm volatile(
        "mma.sync.aligned.m16n8k16.row.col.f32.f16.f16.f32 "
        "{%0,%1,%2,%3}, {%4,%5,%6,%7}, {%8,%9}, {%0,%1,%2,%3};"
        : "+f"(c[0]), "+f"(c[1]), "+f"(c[2]), "+f"(c[3])
        : "r"(a[0]), "r"(a[1]), "r"(a[2]), "r"(a[3]), "r"(b[0]), "r"(b[1]));
}

__device__ __forceinline__ void ldsm_x4(uint32_t r[4], uint32_t addr) {
    asm volatile("ldmatrix.sync.aligned.m8n8.x4.shared.b16 {%0,%1,%2,%3}, [%4];"
        : "=r"(r[0]), "=r"(r[1]), "=r"(r[2]), "=r"(r[3]) : "r"(addr));
}
__device__ __forceinline__ void ldsm_x2(uint32_t r[2], uint32_t addr) {
    asm volatile("ldmatrix.sync.aligned.m8n8.x2.shared.b16 {%0,%1}, [%2];"
        : "=r"(r[0]), "=r"(r[1]) : "r"(addr));
}
__device__ __forceinline__ void cp_async16(uint32_t dst, const void* src) {
    asm volatile("cp.async.cg.shared.global [%0], [%1], 16;" :: "r"(dst), "l"(src));
}
#define CP_COMMIT() asm volatile("cp.async.commit_group;" ::: "memory")
#define CP_WAIT(n)  asm volatile("cp.async.wait_group %0;" :: "n"(n) : "memory")

// ================= FP16 tensor-core GEMM (templated on M-tile) =================
// C[m,n] = sum_k A[m,k]*B[n,k]; fp16 inputs (K contiguous), fp32 out.
// CTA tile (MT*64)x128, BK=64, 3-stage cp.async, 512 thr (4x4 warps).
#define GTN 128
#define GBK 64
#define GNS 3
#define ROWB 144                 // smem row stride bytes (64 halves + 8 pad)

template<int MT>                  // 4 -> 256 rows, 2 -> 128 rows
__global__ void __launch_bounds__(512, 1)
hgemm_kernel(const __half* __restrict__ A, const __half* __restrict__ Bw,
             float* __restrict__ C, int N, int K) {
    constexpr int GTM = MT * 64;
    constexpr int A_ST = GTM * ROWB;
    constexpr int B_ST = GTN * ROWB;
    constexpr int STB = A_ST + B_ST;
    constexpr int ACH = GTM * 8;          // 16B chunks of A per stage
    constexpr int TOT = ACH + GTN * 8;

    extern __shared__ __align__(128) char smem[];
    uint32_t sb = smem_u32(smem);
    int t = threadIdx.x;
    int lane = t & 31, warp = t >> 5;
    int wm = warp >> 2;        // 0..3
    int wn = warp & 3;         // 0..3

    const __half* Ag = A + (size_t)(blockIdx.y * GTM) * K;
    const __half* Bg = Bw + (size_t)(blockIdx.x * GTN) * K;
    int nk = K / GBK;

    int j = lane >> 3, r8 = lane & 7;
    uint32_t a_off = (uint32_t)((wm * (MT * 16) + (j & 1) * 8 + r8) * ROWB + (j >> 1) * 16);
    uint32_t b_off = (uint32_t)(A_ST + (wn * 32 + r8) * ROWB + (j & 1) * 16);

    auto load_stage = [&](int slot, int kt) {
        uint32_t sdst = sb + slot * STB;
        int koff = kt * GBK;
#pragma unroll
        for (int c0 = 0; c0 < TOT; c0 += 512) {
            int c = c0 + t;
            if (c < ACH) {
                int r = c >> 3, ch = c & 7;
                cp_async16(sdst + r * ROWB + ch * 16, Ag + (size_t)r * K + koff + ch * 8);
            } else {
                int c2 = c - ACH;
                int r = c2 >> 3, ch = c2 & 7;
                cp_async16(sdst + A_ST + r * ROWB + ch * 16, Bg + (size_t)r * K + koff + ch * 8);
            }
        }
    };

    for (int s = 0; s < GNS - 1; s++) { load_stage(s, s); CP_COMMIT(); }

    float acc[MT][4][4] = {};

    for (int kt = 0; kt < nk; kt++) {
        CP_WAIT(GNS - 2);
        __syncthreads();
        uint32_t sbase = sb + (kt % GNS) * STB;
#pragma unroll
        for (int ks = 0; ks < 4; ks++) {
            uint32_t kb = ks * 32;
            uint32_t aF[MT][4], bF[4][2];
#pragma unroll
            for (int mt = 0; mt < MT; mt++)
                ldsm_x4(aF[mt], sbase + a_off + mt * 16 * ROWB + kb);
#pragma unroll
            for (int nt = 0; nt < 4; nt++)
                ldsm_x2(bF[nt], sbase + b_off + nt * 8 * ROWB + kb);
#pragma unroll
            for (int mt = 0; mt < MT; mt++)
#pragma unroll
                for (int nt = 0; nt < 4; nt++)
                    mma_f16(acc[mt][nt], aF[mt], bF[nt]);
        }
        __syncthreads();
        if (kt + GNS - 1 < nk) load_stage((kt + GNS - 1) % GNS, kt + GNS - 1);
        CP_COMMIT();
    }

    int g = lane >> 2, tig = lane & 3;
#pragma unroll
    for (int mt = 0; mt < MT; mt++) {
#pragma unroll
        for (int nt = 0; nt < 4; nt++) {
            int row = blockIdx.y * GTM + wm * (MT * 16) + mt * 16 + g;
            int col = blockIdx.x * GTN + wn * 32 + nt * 8 + 2 * tig;
            float2 lo = {acc[mt][nt][0], acc[mt][nt][1]};
            float2 hi = {acc[mt][nt][2], acc[mt][nt][3]};
            *(float2*)&C[(size_t)row * N + col] = lo;
            *(float2*)&C[(size_t)(row + 8) * N + col] = hi;
        }
    }
}

// ================= bilinear via tensor cores =================
// For pair p: acc[b,f] = sum_e Vi[b,e]*biW[p,f,e]; out = acc*Vj[b,f] (+ *a_i*a_j).
// Block: 128 batch rows x 64 f cols, K=64, one shot. 256 thr = 8 warps (4m x 2n).
#define BL_VI 0
#define BL_VJ 18432
#define BL_W  36864
#define BL_GA 46080
#define BL_SMEM 46592

__global__ void __launch_bounds__(256)
bilinear_mma_kernel(const __half* __restrict__ biWh) {
    __shared__ __align__(128) char sm[BL_SMEM];
    uint32_t sb = smem_u32(sm);
    int t = threadIdx.x;
    int lane = t & 31, warp = t >> 5;
    int wm = warp >> 1;   // 0..3 -> 32 rows
    int wn = warp & 1;    // 0..1 -> 32 cols

    int p = blockIdx.y;
    int i = 0, rem = p, cnt = 15;
    while (rem >= cnt) { rem -= cnt; i++; cnt--; }
    int jf = i + 1 + rem;
    int b0 = blockIdx.x * 128;

    // load Vi (128x64h), Vj (128x64h), W (64x64h) via cp.async; 2560 chunks
#pragma unroll
    for (int c0 = 0; c0 < 2560; c0 += 256) {
        int c = c0 + t;
        if (c < 1024) {
            int r = c >> 3, ch = c & 7;
            cp_async16(sb + BL_VI + r * ROWB + ch * 16,
                       g_embh + (size_t)(b0 + r) * 1024 + i * 64 + ch * 8);
        } else if (c < 2048) {
            int r = (c - 1024) >> 3, ch = c & 7;
            cp_async16(sb + BL_VJ + r * ROWB + ch * 16,
                       g_embh + (size_t)(b0 + r) * 1024 + jf * 64 + ch * 8);
        } else {
            int r = (c - 2048) >> 3, ch = c & 7;
            cp_async16(sb + BL_W + r * ROWB + ch * 16,
                       biWh + (size_t)p * 4096 + r * 64 + ch * 8);
        }
    }
    if (t < 128) {
        int b = b0 + t;
        *(float*)(sm + BL_GA + t * 4) = g_a[b * 16 + i] * g_a[b * 16 + jf];
    }
    CP_COMMIT();
    CP_WAIT(0);
    __syncthreads();

    int j4 = lane >> 3, r8 = lane & 7;
    uint32_t a_off = sb + BL_VI + (uint32_t)((wm * 32 + (j4 & 1) * 8 + r8) * ROWB + (j4 >> 1) * 16);
    uint32_t b_off = sb + BL_W + (uint32_t)((wn * 32 + r8) * ROWB + (j4 & 1) * 16);

    float acc[2][4][4] = {};
#pragma unroll
    for (int ks = 0; ks < 4; ks++) {
        uint32_t kb = ks * 32;
        uint32_t aF[2][4], bF[4][2];
#pragma unroll
        for (int mt = 0; mt < 2; mt++)
            ldsm_x4(aF[mt], a_off + mt * 16 * ROWB + kb);
#pragma unroll
        for (int nt = 0; nt < 4; nt++)
            ldsm_x2(bF[nt], b_off + nt * 8 * ROWB + kb);
#pragma unroll
        for (int mt = 0; mt < 2; mt++)
#pragma unroll
            for (int nt = 0; nt < 4; nt++)
                mma_f16(acc[mt][nt], aF[mt], bF[nt]);
    }

    int g = lane >> 2, tig = lane & 3;
#pragma unroll
    for (int mt = 0; mt < 2; mt++) {
#pragma unroll
        for (int nt = 0; nt < 4; nt++) {
            int col = wn * 32 + nt * 8 + 2 * tig;
#pragma unroll
            for (int h = 0; h < 2; h++) {
                int row = wm * 32 + mt * 16 + g + h * 8;
                __half2 vj = *(__half2*)(sm + BL_VJ + row * ROWB + col * 2);
                float s = *(float*)(sm + BL_GA + row * 4);
                float b0f = acc[mt][nt][h * 2 + 0] * __half2float(vj.x);
                float b1f = acc[mt][nt][h * 2 + 1] * __half2float(vj.y);
                size_t base = (size_t)(b0 + row) * K0 + p * 64 + col;
                *(__half2*)&g_dnn[base] = __floats2half2_rn(b0f, b1f);
                *(__half2*)&g_dnn[base + 7680] = __floats2half2_rn(b0f * s, b1f * s);
            }
        }
    }
}

// ---------------- f32 -> f16 conversion ----------------
__global__ void f2h_kernel(const float* __restrict__ src, __half* __restrict__ dst, int n) {
    int i = (blockIdx.x * blockDim.x + threadIdx.x) * 4;
    if (i >= n) return;
    float4 v = *(const float4*)(src + i);
    __half2* d = (__half2*)(dst + i);
    d[0] = __floats2half2_rn(v.x, v.y);
    d[1] = __floats2half2_rn(v.z, v.w);
}

// ---------------- embedding (writes fp16 emb) ----------------
__global__ void embed_kernel(const float* __restrict__ sparse,
                             const float* __restrict__ embW) {
    __shared__ float Ws[64][65];
    __shared__ float Xs[64][65];
    int g = blockIdx.y;
    int b0 = blockIdx.x * 64;
    int t = threadIdx.x;

    for (int idx = t; idx < 4096; idx += 256)
        Ws[idx >> 6][idx & 63] = embW[g * 4096 + idx];
    for (int idx = t; idx < 4096; idx += 256) {
        int r = idx >> 6, f = idx & 63;
        Xs[r][f] = sparse[(size_t)(b0 + r) * 1024 + g * 64 + f];
    }
    __syncthreads();

    int rq = t >> 4, eq = t & 15;
    float acc[4][4] = {};
#pragma unroll 8
    for (int f = 0; f < 64; f++) {
        float xa[4], wb[4];
#pragma unroll
        for (int i = 0; i < 4; i++) xa[i] = Xs[rq * 4 + i][f];
#pragma unroll
        for (int j = 0; j < 4; j++) wb[j] = Ws[eq * 4 + j][f];
#pragma unroll
        for (int i = 0; i < 4; i++)
#pragma unroll
            for (int j = 0; j < 4; j++) acc[i][j] += xa[i] * wb[j];
    }
#pragma unroll
    for (int i = 0; i < 4; i++) {
        size_t base = (size_t)(b0 + rq * 4 + i) * 1024 + g * 64 + eq * 4;
        *(__half2*)&g_embh[base] = __floats2half2_rn(acc[i][0], acc[i][1]);
        *(__half2*)&g_embh[base + 2] = __floats2half2_rn(acc[i][2], acc[i][3]);
    }
}

// ---------------- SENet gates (reads fp16 emb) ----------------
__global__ void senet_kernel(const float* __restrict__ seW1,
                             const float* __restrict__ seW2) {
    int warp = (blockIdx.x * blockDim.x + threadIdx.x) >> 5;
    int lane = threadIdx.x & 31;
    if (warp >= BATCH) return;
    const __half* row = g_embh + (size_t)warp * 1024;

    float zs[16];
#pragma unroll
    for (int g = 0; g < 16; g++) {
        float s = __half2float(row[g * 64 + lane]) + __half2float(row[g * 64 + 32 + lane]);
#pragma unroll
        for (int o = 16; o; o >>= 1) s += __shfl_xor_sync(0xFFFFFFFFu, s, o);
        zs[g] = s * (1.0f / 64.0f);
    }
    float hv[4];
#pragma unroll
    for (int tt = 0; tt < 4; tt++) {
        float s = 0.f;
#pragma unroll
        for (int g = 0; g < 16; g++) s += zs[g] * seW1[tt * 16 + g];
        hv[tt] = fmaxf(s, 0.f);
    }
    if (lane < 16) {
        float s = 0.f;
#pragma unroll
        for (int tt = 0; tt < 4; tt++) s += hv[tt] * seW2[lane * 4 + tt];
        g_a[warp * 16 + lane] = fmaxf(s, 0.f);
    }
}

// ---------------- dense copy (fp16) ----------------
__global__ void dense_copy_kernel(const float* __restrict__ dense) {
    int idx = blockIdx.x * blockDim.x + threadIdx.x;
    if (idx >= BATCH * 64) return;
    int b = idx >> 6, d = idx & 63;
    g_dnn[(size_t)b * K0 + 15360 + d] = __float2half_rn(dense[idx]);
}

// ---------------- linear logit ----------------
__global__ void linear_kernel(const float* __restrict__ sparse,
                              const float* __restrict__ dense,
                              const float* __restrict__ linW,
                              const float* __restrict__ linb) {
    int warp = (blockIdx.x * blockDim.x + threadIdx.x) >> 5;
    int lane = threadIdx.x & 31;
    if (warp >= BATCH) return;
    const float* s = sparse + (size_t)warp * 1024;
    float acc = 0.f;
    for (int k = lane; k < 1024; k += 32) acc += s[k] * linW[k];
    for (int k = lane; k < 64; k += 32) acc += dense[warp * 64 + k] * linW[1024 + k];
#pragma unroll
    for (int o = 16; o; o >>= 1) acc += __shfl_xor_sync(0xFFFFFFFFu, acc, o);
    if (lane == 0) g_lin[warp] = acc + linb[0];
}

// ---------------- batchnorm stats ----------------
__global__ void bn_stats_kernel(const float* __restrict__ X, int M, int N) {
    int c = blockIdx.x * 32 + threadIdx.x;
    float s = 0.f, q = 0.f;
    for (int r = threadIdx.y; r < M; r += blockDim.y) {
        float v = X[(size_t)r * N + c];
        s += v; q += v * v;
    }
    __shared__ float ss[8][32], qq[8][32];
    ss[threadIdx.y][threadIdx.x] = s;
    qq[threadIdx.y][threadIdx.x] = q;
    __syncthreads();
    if (threadIdx.y == 0) {
#pragma unroll
        for (int r = 1; r < 8; r++) { s += ss[r][threadIdx.x]; q += qq[r][threadIdx.x]; }
        float m = s / (float)M;
        g_mean[c] = m;
        g_var[c] = q / (float)M - m * m;
    }
}

// ---------------- apply BN + sigmoid -> fp16 ----------------
__global__ void bn_apply_kernel(const float* __restrict__ X, __half* __restrict__ Xh,
                                int M, int N) {
    int idx = blockIdx.x * blockDim.x + threadIdx.x;
    if (idx >= M * N) return;
    int c = idx % N;
    float v = (X[idx] - g_mean[c]) * rsqrtf(g_var[c] + BN_EPS);
    Xh[idx] = __float2half_rn(sigmoidf(v));
}

// ---------------- W3 dot ----------------
__global__ void w3_kernel(const float* __restrict__ W3) {
    int warp = (blockIdx.x * blockDim.x + threadIdx.x) >> 5;
    int lane = threadIdx.x & 31;
    if (warp >= BATCH) return;
    const __half* h = g_h2h + (size_t)warp * 256;
    float acc = 0.f;
#pragma unroll
    for (int k = lane; k < 256; k += 32) acc += __half2float(h[k]) * W3[k];
#pragma unroll
    for (int o = 16; o; o >>= 1) acc += __shfl_xor_sync(0xFFFFFFFFu, acc, o);
    if (lane == 0) g_v[warp] = acc;
}

// ---------------- scalar BN stats ----------------
__global__ void vstats_kernel() {
    __shared__ float ss[1024], qq[1024];
    int t = threadIdx.x;
    float s = 0.f, q = 0.f;
    for (int i = t; i < BATCH; i += 1024) { float v = g_v[i]; s += v; q += v * v; }
    ss[t] = s; qq[t] = q;
    __syncthreads();
    for (int o = 512; o; o >>= 1) {
        if (t < o) { ss[t] += ss[t + o]; qq[t] += qq[t + o]; }
        __syncthreads();
    }
    if (t == 0) {
        float m = ss[0] / (float)BATCH;
        g_s2[0] = m;
        g_s2[1] = qq[0] / (float)BATCH - m * m;
    }
}

// ---------------- final ----------------
__global__ void final_kernel(float* __restrict__ out) {
    int b = blockIdx.x * blockDim.x + threadIdx.x;
    if (b >= BATCH) return;
    float v = (g_v[b] - g_s2[0]) * rsqrtf(g_s2[1] + BN_EPS);
    float dl = sigmoidf(v);
    out[b] = sigmoidf(g_lin[b] + dl);
}

// ---------------- launch ----------------
extern "C" void kernel_launch(void* const* d_in, const int* in_sizes, int n_in,
                              void* d_out, int out_size) {
    const float* sparse = (const float*)d_in[0];
    const float* dense  = (const float*)d_in[1];
    const float* embW   = (const float*)d_in[2];
    const float* linW   = (const float*)d_in[3];
    const float* linb   = (const float*)d_in[4];
    const float* seW1   = (const float*)d_in[5];
    const float* seW2   = (const float*)d_in[6];
    const float* biW    = (const float*)d_in[7];
    const float* W0     = (const float*)d_in[8];
    const float* W1     = (const float*)d_in[10];
    const float* W2     = (const float*)d_in[12];
    const float* W3     = (const float*)d_in[14];

    void *p_dnn, *p_W0h, *p_W1h, *p_W2h, *p_biWh;
    void *p_h0, *p_h1, *p_h2, *p_h0h, *p_h1h, *p_h2h;
    cudaGetSymbolAddress(&p_dnn, g_dnn);
    cudaGetSymbolAddress(&p_W0h, g_W0h);
    cudaGetSymbolAddress(&p_W1h, g_W1h);
    cudaGetSymbolAddress(&p_W2h, g_W2h);
    cudaGetSymbolAddress(&p_biWh, g_biWh);
    cudaGetSymbolAddress(&p_h0, g_h0);
    cudaGetSymbolAddress(&p_h1, g_h1);
    cudaGetSymbolAddress(&p_h2, g_h2);
    cudaGetSymbolAddress(&p_h0h, g_h0h);
    cudaGetSymbolAddress(&p_h1h, g_h1h);
    cudaGetSymbolAddress(&p_h2h, g_h2h);

    constexpr int SM4 = GNS * ((256 + 128) * ROWB);   // 165888
    constexpr int SM2 = GNS * ((128 + 128) * ROWB);   // 110592
    cudaFuncSetAttribute(hgemm_kernel<4>, cudaFuncAttributeMaxDynamicSharedMemorySize, SM4);
    cudaFuncSetAttribute(hgemm_kernel<2>, cudaFuncAttributeMaxDynamicSharedMemorySize, SM2);

    // conversions
    f2h_kernel<<<(N0 * K0 / 4 + 255) / 256, 256>>>(W0, (__half*)p_W0h, N0 * K0);
    f2h_kernel<<<(N1 * N0 / 4 + 255) / 256, 256>>>(W1, (__half*)p_W1h, N1 * N0);
    f2h_kernel<<<(N2 * N1 / 4 + 255) / 256, 256>>>(W2, (__half*)p_W2h, N2 * N1);
    f2h_kernel<<<(NPAIRS * 4096 / 4 + 255) / 256, 256>>>(biW, (__half*)p_biWh, NPAIRS * 4096);

    embed_kernel<<<dim3(BATCH / 64, NF), 256>>>(sparse, embW);
    senet_kernel<<<BATCH / 8, 256>>>(seW1, seW2);
    bilinear_mma_kernel<<<dim3(BATCH / 128, NPAIRS), 256>>>((const __half*)p_biWh);
    dense_copy_kernel<<<(BATCH * 64) / 256, 256>>>(dense);
    linear_kernel<<<BATCH / 8, 256>>>(sparse, dense, linW, linb);

    // layer 0: 4096 x 1024, K=15424
    hgemm_kernel<4><<<dim3(N0 / GTN, BATCH / 256), 512, SM4>>>(
        (const __half*)p_dnn, (const __half*)p_W0h, (float*)p_h0, N0, K0);
    bn_stats_kernel<<<N0 / 32, dim3(32, 8)>>>((const float*)p_h0, BATCH, N0);
    bn_apply_kernel<<<(BATCH * N0) / 256, 256>>>((const float*)p_h0, (__half*)p_h0h, BATCH, N0);

    // layer 1: 4096 x 512, K=1024
    hgemm_kernel<2><<<dim3(N1 / GTN, BATCH / 128), 512, SM2>>>(
        (const __half*)p_h0h, (const __half*)p_W1h, (float*)p_h1, N1, N0);
    bn_stats_kernel<<<N1 / 32, dim3(32, 8)>>>((const float*)p_h1, BATCH, N1);
    bn_apply_kernel<<<(BATCH * N1) / 256, 256>>>((const float*)p_h1, (__half*)p_h1h, BATCH, N1);

    // layer 2: 4096 x 256, K=512
    hgemm_kernel<2><<<dim3(N2 / GTN, BATCH / 128), 512, SM2>>>(
        (const __half*)p_h1h, (const __half*)p_W2h, (float*)p_h2, N2, N1);
    bn_stats_kernel<<<N2 / 32, dim3(32, 8)>>>((const float*)p_h2, BATCH, N2);
    bn_apply_kernel<<<(BATCH * N2) / 256, 256>>>((const float*)p_h2, (__half*)p_h2h, BATCH, N2);

    // layer 3 + final
    w3_kernel<<<BATCH / 8, 256>>>(W3);
    vstats_kernel<<<1, 1024>>>();
    final_kernel<<<BATCH / 256, 256>>>((float*)d_out);
}

// round 6
// speedup vs baseline: 4.3492x; 1.0022x over previous
#include <cuda_runtime.h>
#include <cuda_fp16.h>
#include <cstdint>

#define BATCH 4096
#define NF 16
#define FS 64
#define EMBD 64
#define NPAIRS 120
#define K0 15424   // 2*120*64 + 64
#define N0 1024
#define N1 512
#define N2 256
#define BN_EPS 1e-5f

// ---------------- scratch (device globals; no allocations) ----------------
__device__ __align__(16) __half g_sparseh[BATCH * NF * FS];    // 8 MB fp16 sparse
__device__ __align__(16) __half g_embWh[NF * EMBD * FS];
__device__ __align__(16) __half g_embh[BATCH * NF * EMBD];     // 8 MB fp16 emb
__device__ float  g_a[BATCH * NF];
__device__ __align__(16) __half g_dnn[(size_t)BATCH * K0];     // 126 MB fp16 dnn_in
__device__ __align__(16) __half g_W0h[(size_t)N0 * K0];
__device__ __align__(16) __half g_W1h[N1 * N0];
__device__ __align__(16) __half g_W2h[N2 * N1];
__device__ __align__(16) __half g_biWh[NPAIRS * EMBD * EMBD];
__device__ __align__(16) float  g_h0[BATCH * N0];
__device__ __align__(16) float  g_h1[BATCH * N1];
__device__ __align__(16) float  g_h2[BATCH * N2];
__device__ __align__(16) __half g_h0h[BATCH * N0];
__device__ __align__(16) __half g_h1h[BATCH * N1];
__device__ __align__(16) __half g_h2h[BATCH * N2];
__device__ float g_v[BATCH];
__device__ float g_lin[BATCH];
__device__ float g_mean[N0];
__device__ float g_var[N0];
__device__ float g_s2[2];

__device__ __forceinline__ float sigmoidf(float x) {
    return 1.0f / (1.0f + __expf(-x));
}

__device__ __forceinline__ uint32_t smem_u32(const void* p) {
    uint32_t a;
    asm("{ .reg .u64 t; cvta.to.shared.u64 t, %1; cvt.u32.u64 %0, t; }" : "=r"(a) : "l"(p));
    return a;
}

__device__ __forceinline__ void mma_f16(float c[4], const uint32_t a[4], const uint32_t b[2]) {
    asm volatile(
        "mma.sync.aligned.m16n8k16.row.col.f32.f16.f16.f32 "
        "{%0,%1,%2,%3}, {%4,%5,%6,%7}, {%8,%9}, {%0,%1,%2,%3};"
        : "+f"(c[0]), "+f"(c[1]), "+f"(c[2]), "+f"(c[3])
        : "r"(a[0]), "r"(a[1]), "r"(a[2]), "r"(a[3]), "r"(b[0]), "r"(b[1]));
}

__device__ __forceinline__ void ldsm_x4(uint32_t r[4], uint32_t addr) {
    asm volatile("ldmatrix.sync.aligned.m8n8.x4.shared.b16 {%0,%1,%2,%3}, [%4];"
        : "=r"(r[0]), "=r"(r[1]), "=r"(r[2]), "=r"(r[3]) : "r"(addr));
}
__device__ __forceinline__ void ldsm_x2(uint32_t r[2], uint32_t addr) {
    asm volatile("ldmatrix.sync.aligned.m8n8.x2.shared.b16 {%0,%1}, [%2];"
        : "=r"(r[0]), "=r"(r[1]) : "r"(addr));
}
__device__ __forceinline__ void cp_async16(uint32_t dst, const void* src) {
    asm volatile("cp.async.cg.shared.global [%0], [%1], 16;" :: "r"(dst), "l"(src));
}
#define CP_COMMIT() asm volatile("cp.async.commit_group;" ::: "memory")
#define CP_WAIT(n)  asm volatile("cp.async.wait_group %0;" :: "n"(n) : "memory")

#define ROWB 144                 // smem row stride bytes (64 halves + 8 pad)

// ================= FP16 GEMM: CTA 128x256, warp 64x64, 256 thr =================
// C[m,n] = sum_k A[m,k]*B[n,k]; fp16 row-major (K contiguous), fp32 out.
#define GTM 128
#define GTN 256
#define GBK 64
#define GNS 3
#define A_ST (GTM * ROWB)        // 18432
#define B_ST (GTN * ROWB)        // 36864
#define STB  (A_ST + B_ST)       // 55296
#define GSMEM (GNS * STB)        // 165888

__global__ void __launch_bounds__(256, 1)
hgemm_kernel(const __half* __restrict__ A, const __half* __restrict__ Bw,
             float* __restrict__ C, int N, int K) {
    extern __shared__ __align__(128) char smem[];
    uint32_t sb = smem_u32(smem);
    int t = threadIdx.x;
    int lane = t & 31, warp = t >> 5;
    int wm = warp & 1;         // 2 x 64 rows
    int wn = warp >> 1;        // 4 x 64 cols

    const __half* Ag = A + (size_t)(blockIdx.y * GTM) * K;
    const __half* Bg = Bw + (size_t)(blockIdx.x * GTN) * K;
    int nk = K / GBK;

    int q = lane >> 3, r8 = lane & 7;
    // A frags: lanes 0-7 rows+0 k0 | 8-15 rows+8 k0 | 16-23 rows+0 k8 | 24-31 rows+8 k8
    uint32_t a_off = (uint32_t)((wm * 64 + (q & 1) * 8 + r8) * ROWB + (q >> 1) * 16);
    // B frags: lanes 0-7 cols+0 k0 | 8-15 cols+0 k8 | 16-23 cols+8 k0 | 24-31 cols+8 k8
    uint32_t b_off = (uint32_t)(A_ST + (wn * 64 + (q >> 1) * 8 + r8) * ROWB + (q & 1) * 16);

    auto load_stage = [&](int slot, int kt) {
        uint32_t sdst = sb + slot * STB;
        int koff = kt * GBK;
#pragma unroll
        for (int c0 = 0; c0 < 3072; c0 += 256) {
            int c = c0 + t;
            if (c < 1024) {
                int r = c >> 3, ch = c & 7;
                cp_async16(sdst + r * ROWB + ch * 16, Ag + (size_t)r * K + koff + ch * 8);
            } else {
                int c2 = c - 1024;
                int r = c2 >> 3, ch = c2 & 7;
                cp_async16(sdst + A_ST + r * ROWB + ch * 16, Bg + (size_t)r * K + koff + ch * 8);
            }
        }
    };

    for (int s = 0; s < GNS - 1; s++) { load_stage(s, s); CP_COMMIT(); }

    float acc[4][8][4] = {};   // 4 m-frags x 8 n-frags

    for (int kt = 0; kt < nk; kt++) {
        CP_WAIT(GNS - 2);
        __syncthreads();
        uint32_t sbase = sb + (kt % GNS) * STB;
#pragma unroll
        for (int ks = 0; ks < 4; ks++) {
            uint32_t kb = ks * 32;
            uint32_t aF[4][4], bF[4][4];
#pragma unroll
            for (int mt = 0; mt < 4; mt++)
                ldsm_x4(aF[mt], sbase + a_off + mt * 16 * ROWB + kb);
#pragma unroll
            for (int ng = 0; ng < 4; ng++)
                ldsm_x4(bF[ng], sbase + b_off + ng * 16 * ROWB + kb);
#pragma unroll
            for (int mt = 0; mt < 4; mt++)
#pragma unroll
                for (int ng = 0; ng < 4; ng++) {
                    mma_f16(acc[mt][ng * 2 + 0], aF[mt], &bF[ng][0]);
                    mma_f16(acc[mt][ng * 2 + 1], aF[mt], &bF[ng][2]);
                }
        }
        __syncthreads();
        if (kt + GNS - 1 < nk) load_stage((kt + GNS - 1) % GNS, kt + GNS - 1);
        CP_COMMIT();
    }

    int g = lane >> 2, tig = lane & 3;
#pragma unroll
    for (int mt = 0; mt < 4; mt++) {
#pragma unroll
        for (int nf = 0; nf < 8; nf++) {
            int row = blockIdx.y * GTM + wm * 64 + mt * 16 + g;
            int col = blockIdx.x * GTN + wn * 64 + nf * 8 + 2 * tig;
            float2 lo = {acc[mt][nf][0], acc[mt][nf][1]};
            float2 hi = {acc[mt][nf][2], acc[mt][nf][3]};
            *(float2*)&C[(size_t)row * N + col] = lo;
            *(float2*)&C[(size_t)(row + 8) * N + col] = hi;
        }
    }
}

// ================= embedding via tensor cores =================
// emb[b,g,e] = sum_f sparse[b,g*64+f] * embW[g,e,f]; 128 rows x 64 e, K=64.
#define EM_X 0
#define EM_W 18432
#define EM_SMEM 27648

__global__ void __launch_bounds__(256)
embed_mma_kernel() {
    __shared__ __align__(128) char sm[EM_SMEM];
    uint32_t sb = smem_u32(sm);
    int t = threadIdx.x;
    int lane = t & 31, warp = t >> 5;
    int wm = warp >> 1;   // 0..3 -> 32 rows
    int wn = warp & 1;    // 0..1 -> 32 cols
    int gg = blockIdx.y;
    int b0 = blockIdx.x * 128;

#pragma unroll
    for (int c0 = 0; c0 < 1536; c0 += 256) {
        int c = c0 + t;
        if (c < 1024) {
            int r = c >> 3, ch = c & 7;
            cp_async16(sb + EM_X + r * ROWB + ch * 16,
                       g_sparseh + (size_t)(b0 + r) * 1024 + gg * 64 + ch * 8);
        } else {
            int r = (c - 1024) >> 3, ch = c & 7;
            cp_async16(sb + EM_W + r * ROWB + ch * 16,
                       g_embWh + gg * 4096 + r * 64 + ch * 8);
        }
    }
    CP_COMMIT();
    CP_WAIT(0);
    __syncthreads();

    int q = lane >> 3, r8 = lane & 7;
    uint32_t a_off = sb + EM_X + (uint32_t)((wm * 32 + (q & 1) * 8 + r8) * ROWB + (q >> 1) * 16);
    uint32_t b_off = sb + EM_W + (uint32_t)((wn * 32 + r8) * ROWB + (q & 1) * 16);

    float acc[2][4][4] = {};
#pragma unroll
    for (int ks = 0; ks < 4; ks++) {
        uint32_t kb = ks * 32;
        uint32_t aF[2][4], bF[4][2];
#pragma unroll
        for (int mt = 0; mt < 2; mt++)
            ldsm_x4(aF[mt], a_off + mt * 16 * ROWB + kb);
#pragma unroll
        for (int nt = 0; nt < 4; nt++)
            ldsm_x2(bF[nt], b_off + nt * 8 * ROWB + kb);
#pragma unroll
        for (int mt = 0; mt < 2; mt++)
#pragma unroll
            for (int nt = 0; nt < 4; nt++)
                mma_f16(acc[mt][nt], aF[mt], bF[nt]);
    }

    int g = lane >> 2, tig = lane & 3;
#pragma unroll
    for (int mt = 0; mt < 2; mt++) {
#pragma unroll
        for (int nt = 0; nt < 4; nt++) {
            int col = wn * 32 + nt * 8 + 2 * tig;
#pragma unroll
            for (int h = 0; h < 2; h++) {
                int row = wm * 32 + mt * 16 + g + h * 8;
                size_t base = (size_t)(b0 + row) * 1024 + gg * 64 + col;
                *(__half2*)&g_embh[base] =
                    __floats2half2_rn(acc[mt][nt][h * 2 + 0], acc[mt][nt][h * 2 + 1]);
            }
        }
    }
}

// ================= bilinear via tensor cores =================
#define BL_VI 0
#define BL_VJ 18432
#define BL_W  36864
#define BL_GA 46080
#define BL_SMEM 46592

__global__ void __launch_bounds__(256)
bilinear_mma_kernel(const __half* __restrict__ biWh) {
    __shared__ __align__(128) char sm[BL_SMEM];
    uint32_t sb = smem_u32(sm);
    int t = threadIdx.x;
    int lane = t & 31, warp = t >> 5;
    int wm = warp >> 1;   // 0..3 -> 32 rows
    int wn = warp & 1;    // 0..1 -> 32 cols

    int p = blockIdx.y;
    int i = 0, rem = p, cnt = 15;
    while (rem >= cnt) { rem -= cnt; i++; cnt--; }
    int jf = i + 1 + rem;
    int b0 = blockIdx.x * 128;

#pragma unroll
    for (int c0 = 0; c0 < 2560; c0 += 256) {
        int c = c0 + t;
        if (c < 1024) {
            int r = c >> 3, ch = c & 7;
            cp_async16(sb + BL_VI + r * ROWB + ch * 16,
                       g_embh + (size_t)(b0 + r) * 1024 + i * 64 + ch * 8);
        } else if (c < 2048) {
            int r = (c - 1024) >> 3, ch = c & 7;
            cp_async16(sb + BL_VJ + r * ROWB + ch * 16,
                       g_embh + (size_t)(b0 + r) * 1024 + jf * 64 + ch * 8);
        } else {
            int r = (c - 2048) >> 3, ch = c & 7;
            cp_async16(sb + BL_W + r * ROWB + ch * 16,
                       biWh + (size_t)p * 4096 + r * 64 + ch * 8);
        }
    }
    if (t < 128) {
        int b = b0 + t;
        *(float*)(sm + BL_GA + t * 4) = g_a[b * 16 + i] * g_a[b * 16 + jf];
    }
    CP_COMMIT();
    CP_WAIT(0);
    __syncthreads();

    int q = lane >> 3, r8 = lane & 7;
    uint32_t a_off = sb + BL_VI + (uint32_t)((wm * 32 + (q & 1) * 8 + r8) * ROWB + (q >> 1) * 16);
    uint32_t b_off = sb + BL_W + (uint32_t)((wn * 32 + r8) * ROWB + (q & 1) * 16);

    float acc[2][4][4] = {};
#pragma unroll
    for (int ks = 0; ks < 4; ks++) {
        uint32_t kb = ks * 32;
        uint32_t aF[2][4], bF[4][2];
#pragma unroll
        for (int mt = 0; mt < 2; mt++)
            ldsm_x4(aF[mt], a_off + mt * 16 * ROWB + kb);
#pragma unroll
        for (int nt = 0; nt < 4; nt++)
            ldsm_x2(bF[nt], b_off + nt * 8 * ROWB + kb);
#pragma unroll
        for (int mt = 0; mt < 2; mt++)
#pragma unroll
            for (int nt = 0; nt < 4; nt++)
                mma_f16(acc[mt][nt], aF[mt], bF[nt]);
    }

    int g = lane >> 2, tig = lane & 3;
#pragma unroll
    for (int mt = 0; mt < 2; mt++) {
#pragma unroll
        for (int nt = 0; nt < 4; nt++) {
            int col = wn * 32 + nt * 8 + 2 * tig;
#pragma unroll
            for (int h = 0; h < 2; h++) {
                int row = wm * 32 + mt * 16 + g + h * 8;
                __half2 vj = *(__half2*)(sm + BL_VJ + row * ROWB + col * 2);
                float s = *(float*)(sm + BL_GA + row * 4);
                float b0f = acc[mt][nt][h * 2 + 0] * __half2float(vj.x);
                float b1f = acc[mt][nt][h * 2 + 1] * __half2float(vj.y);
                size_t base = (size_t)(b0 + row) * K0 + p * 64 + col;
                *(__half2*)&g_dnn[base] = __floats2half2_rn(b0f, b1f);
                *(__half2*)&g_dnn[base + 7680] = __floats2half2_rn(b0f * s, b1f * s);
            }
        }
    }
}

// ---------------- f32 -> f16 conversion ----------------
__global__ void f2h_kernel(const float* __restrict__ src, __half* __restrict__ dst, int n) {
    int i = (blockIdx.x * blockDim.x + threadIdx.x) * 4;
    if (i >= n) return;
    float4 v = *(const float4*)(src + i);
    __half2* d = (__half2*)(dst + i);
    d[0] = __floats2half2_rn(v.x, v.y);
    d[1] = __floats2half2_rn(v.z, v.w);
}

// ---------------- SENet gates ----------------
__global__ void senet_kernel(const float* __restrict__ seW1,
                             const float* __restrict__ seW2) {
    int warp = (blockIdx.x * blockDim.x + threadIdx.x) >> 5;
    int lane = threadIdx.x & 31;
    if (warp >= BATCH) return;
    const __half* row = g_embh + (size_t)warp * 1024;

    float zs[16];
#pragma unroll
    for (int g = 0; g < 16; g++) {
        float s = __half2float(row[g * 64 + lane]) + __half2float(row[g * 64 + 32 + lane]);
#pragma unroll
        for (int o = 16; o; o >>= 1) s += __shfl_xor_sync(0xFFFFFFFFu, s, o);
        zs[g] = s * (1.0f / 64.0f);
    }
    float hv[4];
#pragma unroll
    for (int tt = 0; tt < 4; tt++) {
        float s = 0.f;
#pragma unroll
        for (int g = 0; g < 16; g++) s += zs[g] * seW1[tt * 16 + g];
        hv[tt] = fmaxf(s, 0.f);
    }
    if (lane < 16) {
        float s = 0.f;
#pragma unroll
        for (int tt = 0; tt < 4; tt++) s += hv[tt] * seW2[lane * 4 + tt];
        g_a[warp * 16 + lane] = fmaxf(s, 0.f);
    }
}

// ---------------- dense copy (fp16) ----------------
__global__ void dense_copy_kernel(const float* __restrict__ dense) {
    int idx = blockIdx.x * blockDim.x + threadIdx.x;
    if (idx >= BATCH * 64) return;
    int b = idx >> 6, d = idx & 63;
    g_dnn[(size_t)b * K0 + 15360 + d] = __float2half_rn(dense[idx]);
}

// ---------------- linear logit ----------------
__global__ void linear_kernel(const float* __restrict__ sparse,
                              const float* __restrict__ dense,
                              const float* __restrict__ linW,
                              const float* __restrict__ linb) {
    int warp = (blockIdx.x * blockDim.x + threadIdx.x) >> 5;
    int lane = threadIdx.x & 31;
    if (warp >= BATCH) return;
    const float* s = sparse + (size_t)warp * 1024;
    float acc = 0.f;
    for (int k = lane; k < 1024; k += 32) acc += s[k] * linW[k];
    for (int k = lane; k < 64; k += 32) acc += dense[warp * 64 + k] * linW[1024 + k];
#pragma unroll
    for (int o = 16; o; o >>= 1) acc += __shfl_xor_sync(0xFFFFFFFFu, acc, o);
    if (lane == 0) g_lin[warp] = acc + linb[0];
}

// ---------------- batchnorm stats ----------------
__global__ void bn_stats_kernel(const float* __restrict__ X, int M, int N) {
    int c = blockIdx.x * 32 + threadIdx.x;
    float s = 0.f, q = 0.f;
    for (int r = threadIdx.y; r < M; r += blockDim.y) {
        float v = X[(size_t)r * N + c];
        s += v; q += v * v;
    }
    __shared__ float ss[8][32], qq[8][32];
    ss[threadIdx.y][threadIdx.x] = s;
    qq[threadIdx.y][threadIdx.x] = q;
    __syncthreads();
    if (threadIdx.y == 0) {
#pragma unroll
        for (int r = 1; r < 8; r++) { s += ss[r][threadIdx.x]; q += qq[r][threadIdx.x]; }
        float m = s / (float)M;
        g_mean[c] = m;
        g_var[c] = q / (float)M - m * m;
    }
}

// ---------------- apply BN + sigmoid -> fp16 ----------------
__global__ void bn_apply_kernel(const float* __restrict__ X, __half* __restrict__ Xh,
                                int M, int N) {
    int idx = blockIdx.x * blockDim.x + threadIdx.x;
    if (idx >= M * N) return;
    int c = idx % N;
    float v = (X[idx] - g_mean[c]) * rsqrtf(g_var[c] + BN_EPS);
    Xh[idx] = __float2half_rn(sigmoidf(v));
}

// ---------------- W3 dot ----------------
__global__ void w3_kernel(const float* __restrict__ W3) {
    int warp = (blockIdx.x * blockDim.x + threadIdx.x) >> 5;
    int lane = threadIdx.x & 31;
    if (warp >= BATCH) return;
    const __half* h = g_h2h + (size_t)warp * 256;
    float acc = 0.f;
#pragma unroll
    for (int k = lane; k < 256; k += 32) acc += __half2float(h[k]) * W3[k];
#pragma unroll
    for (int o = 16; o; o >>= 1) acc += __shfl_xor_sync(0xFFFFFFFFu, acc, o);
    if (lane == 0) g_v[warp] = acc;
}

// ---------------- scalar BN stats ----------------
__global__ void vstats_kernel() {
    __shared__ float ss[1024], qq[1024];
    int t = threadIdx.x;
    float s = 0.f, q = 0.f;
    for (int i = t; i < BATCH; i += 1024) { float v = g_v[i]; s += v; q += v * v; }
    ss[t] = s; qq[t] = q;
    __syncthreads();
    for (int o = 512; o; o >>= 1) {
        if (t < o) { ss[t] += ss[t + o]; qq[t] += qq[t + o]; }
        __syncthreads();
    }
    if (t == 0) {
        float m = ss[0] / (float)BATCH;
        g_s2[0] = m;
        g_s2[1] = qq[0] / (float)BATCH - m * m;
    }
}

// ---------------- final ----------------
__global__ void final_kernel(float* __restrict__ out) {
    int b = blockIdx.x * blockDim.x + threadIdx.x;
    if (b >= BATCH) return;
    float v = (g_v[b] - g_s2[0]) * rsqrtf(g_s2[1] + BN_EPS);
    float dl = sigmoidf(v);
    out[b] = sigmoidf(g_lin[b] + dl);
}

// ---------------- launch ----------------
extern "C" void kernel_launch(void* const* d_in, const int* in_sizes, int n_in,
                              void* d_out, int out_size) {
    const float* sparse = (const float*)d_in[0];
    const float* dense  = (const float*)d_in[1];
    const float* embW   = (const float*)d_in[2];
    const float* linW   = (const float*)d_in[3];
    const float* linb   = (const float*)d_in[4];
    const float* seW1   = (const float*)d_in[5];
    const float* seW2   = (const float*)d_in[6];
    const float* biW    = (const float*)d_in[7];
    const float* W0     = (const float*)d_in[8];
    const float* W1     = (const float*)d_in[10];
    const float* W2     = (const float*)d_in[12];
    const float* W3     = (const float*)d_in[14];

    void *p_sph, *p_eWh, *p_dnn, *p_W0h, *p_W1h, *p_W2h, *p_biWh;
    void *p_h0, *p_h1, *p_h2, *p_h0h, *p_h1h, *p_h2h;
    cudaGetSymbolAddress(&p_sph, g_sparseh);
    cudaGetSymbolAddress(&p_eWh, g_embWh);
    cudaGetSymbolAddress(&p_dnn, g_dnn);
    cudaGetSymbolAddress(&p_W0h, g_W0h);
    cudaGetSymbolAddress(&p_W1h, g_W1h);
    cudaGetSymbolAddress(&p_W2h, g_W2h);
    cudaGetSymbolAddress(&p_biWh, g_biWh);
    cudaGetSymbolAddress(&p_h0, g_h0);
    cudaGetSymbolAddress(&p_h1, g_h1);
    cudaGetSymbolAddress(&p_h2, g_h2);
    cudaGetSymbolAddress(&p_h0h, g_h0h);
    cudaGetSymbolAddress(&p_h1h, g_h1h);
    cudaGetSymbolAddress(&p_h2h, g_h2h);

    cudaFuncSetAttribute(hgemm_kernel, cudaFuncAttributeMaxDynamicSharedMemorySize, GSMEM);

    // conversions
    f2h_kernel<<<(N0 * K0 / 4 + 255) / 256, 256>>>(W0, (__half*)p_W0h, N0 * K0);
    f2h_kernel<<<(N1 * N0 / 4 + 255) / 256, 256>>>(W1, (__half*)p_W1h, N1 * N0);
    f2h_kernel<<<(N2 * N1 / 4 + 255) / 256, 256>>>(W2, (__half*)p_W2h, N2 * N1);
    f2h_kernel<<<(NPAIRS * 4096 / 4 + 255) / 256, 256>>>(biW, (__half*)p_biWh, NPAIRS * 4096);
    f2h_kernel<<<(BATCH * 1024 / 4 + 255) / 256, 256>>>(sparse, (__half*)p_sph, BATCH * 1024);
    f2h_kernel<<<(NF * 4096 / 4 + 255) / 256, 256>>>(embW, (__half*)p_eWh, NF * 4096);

    embed_mma_kernel<<<dim3(BATCH / 128, NF), 256>>>();
    senet_kernel<<<BATCH / 8, 256>>>(seW1, seW2);
    bilinear_mma_kernel<<<dim3(BATCH / 128, NPAIRS), 256>>>((const __half*)p_biWh);
    dense_copy_kernel<<<(BATCH * 64) / 256, 256>>>(dense);
    linear_kernel<<<BATCH / 8, 256>>>(sparse, dense, linW, linb);

    // layer 0: 4096 x 1024, K=15424
    hgemm_kernel<<<dim3(N0 / GTN, BATCH / GTM), 256, GSMEM>>>(
        (const __half*)p_dnn, (const __half*)p_W0h, (float*)p_h0, N0, K0);
    bn_stats_kernel<<<N0 / 32, dim3(32, 8)>>>((const float*)p_h0, BATCH, N0);
    bn_apply_kernel<<<(BATCH * N0) / 256, 256>>>((const float*)p_h0, (__half*)p_h0h, BATCH, N0);

    // layer 1: 4096 x 512, K=1024
    hgemm_kernel<<<dim3(N1 / GTN, BATCH / GTM), 256, GSMEM>>>(
        (const __half*)p_h0h, (const __half*)p_W1h, (float*)p_h1, N1, N0);
    bn_stats_kernel<<<N1 / 32, dim3(32, 8)>>>((const float*)p_h1, BATCH, N1);
    bn_apply_kernel<<<(BATCH * N1) / 256, 256>>>((const float*)p_h1, (__half*)p_h1h, BATCH, N1);

    // layer 2: 4096 x 256, K=512
    hgemm_kernel<<<dim3(N2 / GTN, BATCH / GTM), 256, GSMEM>>>(
        (const __half*)p_h1h, (const __half*)p_W2h, (float*)p_h2, N2, N1);
    bn_stats_kernel<<<N2 / 32, dim3(32, 8)>>>((const float*)p_h2, BATCH, N2);
    bn_apply_kernel<<<(BATCH * N2) / 256, 256>>>((const float*)p_h2, (__half*)p_h2h, BATCH, N2);

    // layer 3 + final
    w3_kernel<<<BATCH / 8, 256>>>(W3);
    vstats_kernel<<<1, 1024>>>();
    final_kernel<<<BATCH / 256, 256>>>((float*)d_out);
}